// round 6
// baseline (speedup 1.0000x reference)
#include <cuda_runtime.h>

// ---------------------------------------------------------------------------
// VanillaLSTM on GB300 — R3: R2 design + k_out smem-load fix.
// Persistent fp32 LSTM, f32x2 FMA, cp.async double-buffered weight streaming,
// register-resident cell update. B=8192, T=128, E=C=128, G=512, Dout=5.
// ---------------------------------------------------------------------------

#define BB    8192
#define TT    128
#define EE    128
#define CC    128
#define GG    512
#define DOUT  5
#define KTOT  256
#define BM    64
#define NCTA  (BB/BM)
#define EPSV  1e-5f
#define SC_STR 66            // sC row stride (floats): 8B-aligned, breaks conflicts
#define CK    32             // k-rows per weight chunk
#define NCHUNK (KTOT/CK)     // 8
#define WCH   (CK*GG)        // floats per chunk buffer (64KB)

// ------------------------- device scratch ----------------------------------
__device__ float d_mom[TT * 5];
__device__ float d_A[TT * EE], d_Bc[TT * EE], d_Cc[TT * EE];
__device__ __align__(256) float d_Wt[KTOT * GG];
__device__ float d_bias[GG];
__device__ float d_H[(size_t)TT * BB * CC];     // h for all steps [t][b][c]
__device__ float d_Y[(size_t)TT * BB * DOUT];   // pre-BN outputs [t][b][o]

typedef unsigned long long ull;

// ------------------------- helpers -----------------------------------------
__device__ __forceinline__ void ffma2(ull& d, ull a, ull b) {
    asm("fma.rn.f32x2 %0, %1, %2, %0;" : "+l"(d) : "l"(a), "l"(b));
}
__device__ __forceinline__ ull dup2(float x) {
    ull r; unsigned xi = __float_as_uint(x);
    asm("mov.b64 %0, {%1, %1};" : "=l"(r) : "r"(xi));
    return r;
}
__device__ __forceinline__ float2 unpk(ull v) {
    float2 r;
    asm("mov.b64 {%0, %1}, %2;" : "=f"(r.x), "=f"(r.y) : "l"(v));
    return r;
}
__device__ __forceinline__ ull pk2(float x, float y) {
    ull r;
    asm("mov.b64 %0, {%1, %2};" : "=l"(r) : "f"(x), "f"(y));
    return r;
}
__device__ __forceinline__ void cpa16(float* dst, const float* src) {
    unsigned s = (unsigned)__cvta_generic_to_shared(dst);
    asm volatile("cp.async.cg.shared.global [%0], [%1], 16;" :: "r"(s), "l"(src));
}
__device__ __forceinline__ float sigm(float x) {
    return __fdividef(1.f, 1.f + __expf(-x));
}
__device__ __forceinline__ float tanh_f(float x) {
    return 1.f - __fdividef(2.f, __expf(2.f * x) + 1.f);
}

// ------------------------- K1: input moments per t --------------------------
__global__ void k_moments(const float* __restrict__ inp) {
    int t = blockIdx.x, tid = threadIdx.x;
    float su = 0.f, sv = 0.f, suu = 0.f, svv = 0.f, suv = 0.f;
    for (int b = tid; b < BB; b += 256) {
        float2 uv = *(const float2*)(inp + ((size_t)b * TT + t) * 2);
        su += uv.x; sv += uv.y;
        suu += uv.x * uv.x; svv += uv.y * uv.y; suv += uv.x * uv.y;
    }
    __shared__ float red[5][256];
    red[0][tid] = su; red[1][tid] = sv; red[2][tid] = suu;
    red[3][tid] = svv; red[4][tid] = suv;
    __syncthreads();
    for (int s = 128; s > 0; s >>= 1) {
        if (tid < s) {
            #pragma unroll
            for (int m = 0; m < 5; m++) red[m][tid] += red[m][tid + s];
        }
        __syncthreads();
    }
    if (tid < 5) d_mom[t * 5 + tid] = red[tid][0] * (1.0f / BB);
}

// ------------------ K2: BN coeffs + weight transpose + bias -----------------
__global__ void k_prep(const float* __restrict__ W_emb, const float* __restrict__ b_emb,
                       const float* __restrict__ g_emb, const float* __restrict__ be_emb,
                       const float* __restrict__ W_ih, const float* __restrict__ W_hh,
                       const float* __restrict__ b_ih, const float* __restrict__ b_hh) {
    int idx = blockIdx.x * 256 + threadIdx.x;
    if (idx < KTOT * GG) {
        int k = idx / GG, n = idx % GG;
        d_Wt[idx] = (k < CC) ? W_ih[n * CC + k] : W_hh[n * CC + (k - CC)];
    }
    if (idx < GG) d_bias[idx] = b_ih[idx] + b_hh[idx];
    if (idx < TT * EE) {
        int t = idx >> 7, e = idx & 127;
        float w0 = W_emb[e * 2], w1 = W_emb[e * 2 + 1], bb = b_emb[e];
        float mu_u = d_mom[t * 5 + 0], mu_v = d_mom[t * 5 + 1];
        float vu  = d_mom[t * 5 + 2] - mu_u * mu_u;
        float vv  = d_mom[t * 5 + 3] - mu_v * mu_v;
        float cuv = d_mom[t * 5 + 4] - mu_u * mu_v;
        float mu  = w0 * mu_u + w1 * mu_v + bb;
        float var = w0 * w0 * vu + w1 * w1 * vv + 2.f * w0 * w1 * cuv;
        float sc  = g_emb[e] * rsqrtf(var + EPSV);
        d_A[idx]  = sc * w0;
        d_Bc[idx] = sc * w1;
        d_Cc[idx] = sc * (bb - mu) + be_emb[e];
    }
}

// ------------------------- K3: persistent LSTM ------------------------------
// dyn smem: sC[KTOT][SC_STR] (xbn rows 0..127, h rows 128..255) = 67.6KB
//           sW: 2 x WCH weight chunk buffers = 128KB
__global__ void __launch_bounds__(256, 1)
k_lstm(const float* __restrict__ inp) {
    extern __shared__ float smem[];
    float* sC = smem;                       // KTOT * SC_STR
    float* sW = smem + KTOT * SC_STR;       // 2 * WCH

    __shared__ float sBias[GG];
    __shared__ float sUV[BM * 2];
    __shared__ float sAe[EE], sBe[EE], sCe[EE];

    const int tid  = threadIdx.x;
    const int lane = tid & 31;
    const int wid  = tid >> 5;
    const int b0   = blockIdx.x * BM;

    for (int i = tid; i < GG; i += 256) sBias[i] = d_bias[i];
    for (int i = tid; i < CC * BM; i += 256) {
        int k = CC + (i >> 6), r = i & 63;
        sC[k * SC_STR + r] = 0.f;           // h0 = 0
    }

    // prologue: stage chunk 0 into buf0
    for (int i = tid; i < WCH / 4; i += 256) cpa16(sW + i * 4, d_Wt + i * 4);
    asm volatile("cp.async.commit_group;");

    float cst[32];
    #pragma unroll
    for (int i = 0; i < 32; i++) cst[i] = 0.f;

    const int nA = 2 * lane;
    const int nB = 64 + 2 * lane;

    for (int t = 0; t < TT; t++) {
        __syncthreads();   // prev step's h writes done; sAe safe to overwrite
        if (tid < BM) {
            float2 uv = *(const float2*)(inp + ((size_t)(b0 + tid) * TT + t) * 2);
            sUV[tid * 2]     = uv.x;
            sUV[tid * 2 + 1] = uv.y;
        }
        if (tid < EE) {
            sAe[tid] = d_A[t * EE + tid];
            sBe[tid] = d_Bc[t * EE + tid];
            sCe[tid] = d_Cc[t * EE + tid];
        }
        __syncthreads();

        // xbn fill: sC[e][row] = relu(a*u + b*v + c)
        for (int idx = tid; idx < EE * BM; idx += 256) {
            int e = idx >> 6, r = idx & 63;
            float x = fmaf(sAe[e], sUV[r * 2], fmaf(sBe[e], sUV[r * 2 + 1], sCe[e]));
            sC[e * SC_STR + r] = fmaxf(x, 0.f);
        }

        // ---- gates GEMM: 64x512, K=256, pipelined weight chunks ----
        ull acc[8][8];
        #pragma unroll
        for (int i = 0; i < 8; i++)
            #pragma unroll
            for (int j = 0; j < 8; j++) acc[i][j] = 0ULL;

        for (int c = 0; c < NCHUNK; c++) {
            asm volatile("cp.async.wait_group 0;" ::: "memory");
            __syncthreads();   // chunk c data visible; prior chunk's readers done
            {   // prefetch next chunk (wraps to chunk 0 for next t)
                int nc = (c + 1) & (NCHUNK - 1);
                float* dst = sW + ((c + 1) & 1) * WCH;
                const float* src = d_Wt + nc * WCH;
                for (int i = tid; i < WCH / 4; i += 256) cpa16(dst + i * 4, src + i * 4);
                asm volatile("cp.async.commit_group;");
            }
            const float* buf   = sW + (c & 1) * WCH;
            const float* crow0 = sC + (c * CK) * SC_STR + wid * 8;
            #pragma unroll 4
            for (int kk = 0; kk < CK; kk++) {
                const ull* wr = (const ull*)(buf + kk * GG) + lane;
                ull w[8];
                #pragma unroll
                for (int j = 0; j < 8; j++) w[j] = wr[32 * j];

                const ull* c2 = (const ull*)(crow0 + kk * SC_STR);
                float2 f0 = unpk(c2[0]), f1 = unpk(c2[1]);
                float2 f2 = unpk(c2[2]), f3 = unpk(c2[3]);
                ull rp[8];
                rp[0] = dup2(f0.x); rp[1] = dup2(f0.y);
                rp[2] = dup2(f1.x); rp[3] = dup2(f1.y);
                rp[4] = dup2(f2.x); rp[5] = dup2(f2.y);
                rp[6] = dup2(f3.x); rp[7] = dup2(f3.y);

                #pragma unroll
                for (int i = 0; i < 8; i++)
                    #pragma unroll
                    for (int j = 0; j < 8; j++) ffma2(acc[i][j], w[j], rp[i]);
            }
        }
        __syncthreads();   // all warps done reading sC h region

        // ---- cell update in registers; thread owns gate quadruples ----
        // pair A: n in {nA, nA+1} -> acc[i][0](i) [2](f) [4](g) [6](o)
        // pair B: n in {nB, nB+1} -> acc[i][1]    [3]    [5]    [7]
        float* Hbase = d_H + (size_t)t * BB * CC + (size_t)b0 * CC;
        const float biA0 = sBias[nA],          biA1 = sBias[nA + 1];
        const float bfA0 = sBias[CC + nA],     bfA1 = sBias[CC + nA + 1];
        const float bgA0 = sBias[2*CC + nA],   bgA1 = sBias[2*CC + nA + 1];
        const float boA0 = sBias[3*CC + nA],   boA1 = sBias[3*CC + nA + 1];
        const float biB0 = sBias[nB],          biB1 = sBias[nB + 1];
        const float bfB0 = sBias[CC + nB],     bfB1 = sBias[CC + nB + 1];
        const float bgB0 = sBias[2*CC + nB],   bgB1 = sBias[2*CC + nB + 1];
        const float boB0 = sBias[3*CC + nB],   boB1 = sBias[3*CC + nB + 1];

        #pragma unroll
        for (int i = 0; i < 8; i++) {
            const int row = wid * 8 + i;
            // pair A
            {
                float2 gi = unpk(acc[i][0]), gf = unpk(acc[i][2]);
                float2 gg = unpk(acc[i][4]), go = unpk(acc[i][6]);
                float i0 = sigm(gi.x + biA0), f0v = sigm(gf.x + bfA0);
                float g0 = tanh_f(gg.x + bgA0), o0 = sigm(go.x + boA0);
                float c0 = f0v * cst[i*4+0] + i0 * g0; cst[i*4+0] = c0;
                float h0 = o0 * tanh_f(c0);
                float i1 = sigm(gi.y + biA1), f1v = sigm(gf.y + bfA1);
                float g1 = tanh_f(gg.y + bgA1), o1 = sigm(go.y + boA1);
                float c1 = f1v * cst[i*4+1] + i1 * g1; cst[i*4+1] = c1;
                float h1 = o1 * tanh_f(c1);
                sC[(CC + nA)     * SC_STR + row] = h0;
                sC[(CC + nA + 1) * SC_STR + row] = h1;
                *(ull*)(Hbase + (size_t)row * CC + nA) = pk2(h0, h1);
            }
            // pair B
            {
                float2 gi = unpk(acc[i][1]), gf = unpk(acc[i][3]);
                float2 gg = unpk(acc[i][5]), go = unpk(acc[i][7]);
                float i0 = sigm(gi.x + biB0), f0v = sigm(gf.x + bfB0);
                float g0 = tanh_f(gg.x + bgB0), o0 = sigm(go.x + boB0);
                float c0 = f0v * cst[i*4+2] + i0 * g0; cst[i*4+2] = c0;
                float h0 = o0 * tanh_f(c0);
                float i1 = sigm(gi.y + biB1), f1v = sigm(gf.y + bfB1);
                float g1 = tanh_f(gg.y + bgB1), o1 = sigm(go.y + boB1);
                float c1 = f1v * cst[i*4+3] + i1 * g1; cst[i*4+3] = c1;
                float h1 = o1 * tanh_f(c1);
                sC[(CC + nB)     * SC_STR + row] = h0;
                sC[(CC + nB + 1) * SC_STR + row] = h1;
                *(ull*)(Hbase + (size_t)row * CC + nB) = pk2(h0, h1);
            }
        }
    }
}

// ------------------------- K4: output head y = h@Wout^T + b -----------------
__global__ void k_out(const float* __restrict__ W_out, const float* __restrict__ b_out) {
    __shared__ float sW[DOUT * CC];
    __shared__ float sb[DOUT];
    int tid = threadIdx.x;
    for (int i = tid; i < DOUT * CC; i += 256) sW[i] = W_out[i];   // FIX: full 640
    if (tid < DOUT) sb[tid] = b_out[tid];
    __syncthreads();
    size_t g = (size_t)blockIdx.x * 256 + tid;     // over TT*BB
    const float4* h4 = (const float4*)(d_H + g * CC);
    float y0 = sb[0], y1 = sb[1], y2 = sb[2], y3 = sb[3], y4 = sb[4];
    #pragma unroll 8
    for (int c = 0; c < CC / 4; c++) {
        float4 h = h4[c];
        const float4* w4 = (const float4*)sW + c;
        float4 a = w4[0], b = w4[32], d = w4[64], e = w4[96], f = w4[128];
        y0 += h.x * a.x + h.y * a.y + h.z * a.z + h.w * a.w;
        y1 += h.x * b.x + h.y * b.y + h.z * b.z + h.w * b.w;
        y2 += h.x * d.x + h.y * d.y + h.z * d.z + h.w * d.w;
        y3 += h.x * e.x + h.y * e.y + h.z * e.z + h.w * e.w;
        y4 += h.x * f.x + h.y * f.y + h.z * f.z + h.w * f.w;
    }
    float* yo = d_Y + g * DOUT;
    yo[0] = y0; yo[1] = y1; yo[2] = y2; yo[3] = y3; yo[4] = y4;
}

// ------------------------- K5: output BN + ReLU + transpose -----------------
__global__ void k_final(const float* __restrict__ g_out,
                        const float* __restrict__ be_out,
                        float* __restrict__ out) {
    int t = blockIdx.x, tid = threadIdx.x;
    float s1[DOUT], s2[DOUT];
    #pragma unroll
    for (int o = 0; o < DOUT; o++) { s1[o] = 0.f; s2[o] = 0.f; }
    for (int b = tid; b < BB; b += 256) {
        const float* y = d_Y + ((size_t)t * BB + b) * DOUT;
        #pragma unroll
        for (int o = 0; o < DOUT; o++) { float v = y[o]; s1[o] += v; s2[o] += v * v; }
    }
    __shared__ float r1[DOUT][256], r2[DOUT][256];
    #pragma unroll
    for (int o = 0; o < DOUT; o++) { r1[o][tid] = s1[o]; r2[o][tid] = s2[o]; }
    __syncthreads();
    for (int s = 128; s > 0; s >>= 1) {
        if (tid < s) {
            #pragma unroll
            for (int o = 0; o < DOUT; o++) {
                r1[o][tid] += r1[o][tid + s];
                r2[o][tid] += r2[o][tid + s];
            }
        }
        __syncthreads();
    }
    __shared__ float mu[DOUT], rs[DOUT], bb[DOUT];
    if (tid < DOUT) {
        float m = r1[tid][0] * (1.0f / BB);
        float v = r2[tid][0] * (1.0f / BB) - m * m;
        mu[tid] = m;
        rs[tid] = rsqrtf(v + EPSV) * g_out[tid];
        bb[tid] = be_out[tid];
    }
    __syncthreads();
    for (int b = tid; b < BB; b += 256) {
        const float* y = d_Y + ((size_t)t * BB + b) * DOUT;
        float* op = out + ((size_t)b * TT + t) * DOUT;
        #pragma unroll
        for (int o = 0; o < DOUT; o++)
            op[o] = fmaxf(fmaf(y[o] - mu[o], rs[o], bb[o]), 0.f);
    }
}

// ------------------------- launch -------------------------------------------
extern "C" void kernel_launch(void* const* d_in, const int* in_sizes, int n_in,
                              void* d_out, int out_size) {
    const float* inp    = (const float*)d_in[0];
    const float* W_emb  = (const float*)d_in[1];
    const float* b_emb  = (const float*)d_in[2];
    const float* g_emb  = (const float*)d_in[3];
    const float* be_emb = (const float*)d_in[4];
    const float* W_ih   = (const float*)d_in[5];
    const float* W_hh   = (const float*)d_in[6];
    const float* b_ih   = (const float*)d_in[7];
    const float* b_hh   = (const float*)d_in[8];
    const float* W_out  = (const float*)d_in[9];
    const float* b_out  = (const float*)d_in[10];
    const float* g_out  = (const float*)d_in[11];
    const float* be_out = (const float*)d_in[12];
    float* out = (float*)d_out;

    const int lstm_smem = (KTOT * SC_STR + 2 * WCH) * (int)sizeof(float); // 198656
    cudaFuncSetAttribute(k_lstm, cudaFuncAttributeMaxDynamicSharedMemorySize, lstm_smem);

    k_moments<<<TT, 256>>>(inp);
    k_prep<<<512, 256>>>(W_emb, b_emb, g_emb, be_emb, W_ih, W_hh, b_ih, b_hh);
    k_lstm<<<NCTA, 256, lstm_smem>>>(inp);
    k_out<<<(TT * BB) / 256, 256>>>(W_out, b_out);
    k_final<<<TT, 256>>>(g_out, be_out, out);
}

// round 7
// speedup vs baseline: 1.0007x; 1.0007x over previous
#include <cuda_runtime.h>

// ---------------------------------------------------------------------------
// VanillaLSTM on GB300 — R3: R2 design + k_out smem-load fix.
// Persistent fp32 LSTM, f32x2 FMA, cp.async double-buffered weight streaming,
// register-resident cell update. B=8192, T=128, E=C=128, G=512, Dout=5.
// ---------------------------------------------------------------------------

#define BB    8192
#define TT    128
#define EE    128
#define CC    128
#define GG    512
#define DOUT  5
#define KTOT  256
#define BM    64
#define NCTA  (BB/BM)
#define EPSV  1e-5f
#define SC_STR 66            // sC row stride (floats): 8B-aligned, breaks conflicts
#define CK    32             // k-rows per weight chunk
#define NCHUNK (KTOT/CK)     // 8
#define WCH   (CK*GG)        // floats per chunk buffer (64KB)

// ------------------------- device scratch ----------------------------------
__device__ float d_mom[TT * 5];
__device__ float d_A[TT * EE], d_Bc[TT * EE], d_Cc[TT * EE];
__device__ __align__(256) float d_Wt[KTOT * GG];
__device__ float d_bias[GG];
__device__ float d_H[(size_t)TT * BB * CC];     // h for all steps [t][b][c]
__device__ float d_Y[(size_t)TT * BB * DOUT];   // pre-BN outputs [t][b][o]

typedef unsigned long long ull;

// ------------------------- helpers -----------------------------------------
__device__ __forceinline__ void ffma2(ull& d, ull a, ull b) {
    asm("fma.rn.f32x2 %0, %1, %2, %0;" : "+l"(d) : "l"(a), "l"(b));
}
__device__ __forceinline__ ull dup2(float x) {
    ull r; unsigned xi = __float_as_uint(x);
    asm("mov.b64 %0, {%1, %1};" : "=l"(r) : "r"(xi));
    return r;
}
__device__ __forceinline__ float2 unpk(ull v) {
    float2 r;
    asm("mov.b64 {%0, %1}, %2;" : "=f"(r.x), "=f"(r.y) : "l"(v));
    return r;
}
__device__ __forceinline__ ull pk2(float x, float y) {
    ull r;
    asm("mov.b64 %0, {%1, %2};" : "=l"(r) : "f"(x), "f"(y));
    return r;
}
__device__ __forceinline__ void cpa16(float* dst, const float* src) {
    unsigned s = (unsigned)__cvta_generic_to_shared(dst);
    asm volatile("cp.async.cg.shared.global [%0], [%1], 16;" :: "r"(s), "l"(src));
}
__device__ __forceinline__ float sigm(float x) {
    return __fdividef(1.f, 1.f + __expf(-x));
}
__device__ __forceinline__ float tanh_f(float x) {
    return 1.f - __fdividef(2.f, __expf(2.f * x) + 1.f);
}

// ------------------------- K1: input moments per t --------------------------
__global__ void k_moments(const float* __restrict__ inp) {
    int t = blockIdx.x, tid = threadIdx.x;
    float su = 0.f, sv = 0.f, suu = 0.f, svv = 0.f, suv = 0.f;
    for (int b = tid; b < BB; b += 256) {
        float2 uv = *(const float2*)(inp + ((size_t)b * TT + t) * 2);
        su += uv.x; sv += uv.y;
        suu += uv.x * uv.x; svv += uv.y * uv.y; suv += uv.x * uv.y;
    }
    __shared__ float red[5][256];
    red[0][tid] = su; red[1][tid] = sv; red[2][tid] = suu;
    red[3][tid] = svv; red[4][tid] = suv;
    __syncthreads();
    for (int s = 128; s > 0; s >>= 1) {
        if (tid < s) {
            #pragma unroll
            for (int m = 0; m < 5; m++) red[m][tid] += red[m][tid + s];
        }
        __syncthreads();
    }
    if (tid < 5) d_mom[t * 5 + tid] = red[tid][0] * (1.0f / BB);
}

// ------------------ K2: BN coeffs + weight transpose + bias -----------------
__global__ void k_prep(const float* __restrict__ W_emb, const float* __restrict__ b_emb,
                       const float* __restrict__ g_emb, const float* __restrict__ be_emb,
                       const float* __restrict__ W_ih, const float* __restrict__ W_hh,
                       const float* __restrict__ b_ih, const float* __restrict__ b_hh) {
    int idx = blockIdx.x * 256 + threadIdx.x;
    if (idx < KTOT * GG) {
        int k = idx / GG, n = idx % GG;
        d_Wt[idx] = (k < CC) ? W_ih[n * CC + k] : W_hh[n * CC + (k - CC)];
    }
    if (idx < GG) d_bias[idx] = b_ih[idx] + b_hh[idx];
    if (idx < TT * EE) {
        int t = idx >> 7, e = idx & 127;
        float w0 = W_emb[e * 2], w1 = W_emb[e * 2 + 1], bb = b_emb[e];
        float mu_u = d_mom[t * 5 + 0], mu_v = d_mom[t * 5 + 1];
        float vu  = d_mom[t * 5 + 2] - mu_u * mu_u;
        float vv  = d_mom[t * 5 + 3] - mu_v * mu_v;
        float cuv = d_mom[t * 5 + 4] - mu_u * mu_v;
        float mu  = w0 * mu_u + w1 * mu_v + bb;
        float var = w0 * w0 * vu + w1 * w1 * vv + 2.f * w0 * w1 * cuv;
        float sc  = g_emb[e] * rsqrtf(var + EPSV);
        d_A[idx]  = sc * w0;
        d_Bc[idx] = sc * w1;
        d_Cc[idx] = sc * (bb - mu) + be_emb[e];
    }
}

// ------------------------- K3: persistent LSTM ------------------------------
// dyn smem: sC[KTOT][SC_STR] (xbn rows 0..127, h rows 128..255) = 67.6KB
//           sW: 2 x WCH weight chunk buffers = 128KB
__global__ void __launch_bounds__(256, 1)
k_lstm(const float* __restrict__ inp) {
    extern __shared__ float smem[];
    float* sC = smem;                       // KTOT * SC_STR
    float* sW = smem + KTOT * SC_STR;       // 2 * WCH

    __shared__ float sBias[GG];
    __shared__ float sUV[BM * 2];
    __shared__ float sAe[EE], sBe[EE], sCe[EE];

    const int tid  = threadIdx.x;
    const int lane = tid & 31;
    const int wid  = tid >> 5;
    const int b0   = blockIdx.x * BM;

    for (int i = tid; i < GG; i += 256) sBias[i] = d_bias[i];
    for (int i = tid; i < CC * BM; i += 256) {
        int k = CC + (i >> 6), r = i & 63;
        sC[k * SC_STR + r] = 0.f;           // h0 = 0
    }

    // prologue: stage chunk 0 into buf0
    for (int i = tid; i < WCH / 4; i += 256) cpa16(sW + i * 4, d_Wt + i * 4);
    asm volatile("cp.async.commit_group;");

    float cst[32];
    #pragma unroll
    for (int i = 0; i < 32; i++) cst[i] = 0.f;

    const int nA = 2 * lane;
    const int nB = 64 + 2 * lane;

    for (int t = 0; t < TT; t++) {
        __syncthreads();   // prev step's h writes done; sAe safe to overwrite
        if (tid < BM) {
            float2 uv = *(const float2*)(inp + ((size_t)(b0 + tid) * TT + t) * 2);
            sUV[tid * 2]     = uv.x;
            sUV[tid * 2 + 1] = uv.y;
        }
        if (tid < EE) {
            sAe[tid] = d_A[t * EE + tid];
            sBe[tid] = d_Bc[t * EE + tid];
            sCe[tid] = d_Cc[t * EE + tid];
        }
        __syncthreads();

        // xbn fill: sC[e][row] = relu(a*u + b*v + c)
        for (int idx = tid; idx < EE * BM; idx += 256) {
            int e = idx >> 6, r = idx & 63;
            float x = fmaf(sAe[e], sUV[r * 2], fmaf(sBe[e], sUV[r * 2 + 1], sCe[e]));
            sC[e * SC_STR + r] = fmaxf(x, 0.f);
        }

        // ---- gates GEMM: 64x512, K=256, pipelined weight chunks ----
        ull acc[8][8];
        #pragma unroll
        for (int i = 0; i < 8; i++)
            #pragma unroll
            for (int j = 0; j < 8; j++) acc[i][j] = 0ULL;

        for (int c = 0; c < NCHUNK; c++) {
            asm volatile("cp.async.wait_group 0;" ::: "memory");
            __syncthreads();   // chunk c data visible; prior chunk's readers done
            {   // prefetch next chunk (wraps to chunk 0 for next t)
                int nc = (c + 1) & (NCHUNK - 1);
                float* dst = sW + ((c + 1) & 1) * WCH;
                const float* src = d_Wt + nc * WCH;
                for (int i = tid; i < WCH / 4; i += 256) cpa16(dst + i * 4, src + i * 4);
                asm volatile("cp.async.commit_group;");
            }
            const float* buf   = sW + (c & 1) * WCH;
            const float* crow0 = sC + (c * CK) * SC_STR + wid * 8;
            #pragma unroll 4
            for (int kk = 0; kk < CK; kk++) {
                const ull* wr = (const ull*)(buf + kk * GG) + lane;
                ull w[8];
                #pragma unroll
                for (int j = 0; j < 8; j++) w[j] = wr[32 * j];

                const ull* c2 = (const ull*)(crow0 + kk * SC_STR);
                float2 f0 = unpk(c2[0]), f1 = unpk(c2[1]);
                float2 f2 = unpk(c2[2]), f3 = unpk(c2[3]);
                ull rp[8];
                rp[0] = dup2(f0.x); rp[1] = dup2(f0.y);
                rp[2] = dup2(f1.x); rp[3] = dup2(f1.y);
                rp[4] = dup2(f2.x); rp[5] = dup2(f2.y);
                rp[6] = dup2(f3.x); rp[7] = dup2(f3.y);

                #pragma unroll
                for (int i = 0; i < 8; i++)
                    #pragma unroll
                    for (int j = 0; j < 8; j++) ffma2(acc[i][j], w[j], rp[i]);
            }
        }
        __syncthreads();   // all warps done reading sC h region

        // ---- cell update in registers; thread owns gate quadruples ----
        // pair A: n in {nA, nA+1} -> acc[i][0](i) [2](f) [4](g) [6](o)
        // pair B: n in {nB, nB+1} -> acc[i][1]    [3]    [5]    [7]
        float* Hbase = d_H + (size_t)t * BB * CC + (size_t)b0 * CC;
        const float biA0 = sBias[nA],          biA1 = sBias[nA + 1];
        const float bfA0 = sBias[CC + nA],     bfA1 = sBias[CC + nA + 1];
        const float bgA0 = sBias[2*CC + nA],   bgA1 = sBias[2*CC + nA + 1];
        const float boA0 = sBias[3*CC + nA],   boA1 = sBias[3*CC + nA + 1];
        const float biB0 = sBias[nB],          biB1 = sBias[nB + 1];
        const float bfB0 = sBias[CC + nB],     bfB1 = sBias[CC + nB + 1];
        const float bgB0 = sBias[2*CC + nB],   bgB1 = sBias[2*CC + nB + 1];
        const float boB0 = sBias[3*CC + nB],   boB1 = sBias[3*CC + nB + 1];

        #pragma unroll
        for (int i = 0; i < 8; i++) {
            const int row = wid * 8 + i;
            // pair A
            {
                float2 gi = unpk(acc[i][0]), gf = unpk(acc[i][2]);
                float2 gg = unpk(acc[i][4]), go = unpk(acc[i][6]);
                float i0 = sigm(gi.x + biA0), f0v = sigm(gf.x + bfA0);
                float g0 = tanh_f(gg.x + bgA0), o0 = sigm(go.x + boA0);
                float c0 = f0v * cst[i*4+0] + i0 * g0; cst[i*4+0] = c0;
                float h0 = o0 * tanh_f(c0);
                float i1 = sigm(gi.y + biA1), f1v = sigm(gf.y + bfA1);
                float g1 = tanh_f(gg.y + bgA1), o1 = sigm(go.y + boA1);
                float c1 = f1v * cst[i*4+1] + i1 * g1; cst[i*4+1] = c1;
                float h1 = o1 * tanh_f(c1);
                sC[(CC + nA)     * SC_STR + row] = h0;
                sC[(CC + nA + 1) * SC_STR + row] = h1;
                *(ull*)(Hbase + (size_t)row * CC + nA) = pk2(h0, h1);
            }
            // pair B
            {
                float2 gi = unpk(acc[i][1]), gf = unpk(acc[i][3]);
                float2 gg = unpk(acc[i][5]), go = unpk(acc[i][7]);
                float i0 = sigm(gi.x + biB0), f0v = sigm(gf.x + bfB0);
                float g0 = tanh_f(gg.x + bgB0), o0 = sigm(go.x + boB0);
                float c0 = f0v * cst[i*4+2] + i0 * g0; cst[i*4+2] = c0;
                float h0 = o0 * tanh_f(c0);
                float i1 = sigm(gi.y + biB1), f1v = sigm(gf.y + bfB1);
                float g1 = tanh_f(gg.y + bgB1), o1 = sigm(go.y + boB1);
                float c1 = f1v * cst[i*4+3] + i1 * g1; cst[i*4+3] = c1;
                float h1 = o1 * tanh_f(c1);
                sC[(CC + nB)     * SC_STR + row] = h0;
                sC[(CC + nB + 1) * SC_STR + row] = h1;
                *(ull*)(Hbase + (size_t)row * CC + nB) = pk2(h0, h1);
            }
        }
    }
}

// ------------------------- K4: output head y = h@Wout^T + b -----------------
__global__ void k_out(const float* __restrict__ W_out, const float* __restrict__ b_out) {
    __shared__ float sW[DOUT * CC];
    __shared__ float sb[DOUT];
    int tid = threadIdx.x;
    for (int i = tid; i < DOUT * CC; i += 256) sW[i] = W_out[i];   // FIX: full 640
    if (tid < DOUT) sb[tid] = b_out[tid];
    __syncthreads();
    size_t g = (size_t)blockIdx.x * 256 + tid;     // over TT*BB
    const float4* h4 = (const float4*)(d_H + g * CC);
    float y0 = sb[0], y1 = sb[1], y2 = sb[2], y3 = sb[3], y4 = sb[4];
    #pragma unroll 8
    for (int c = 0; c < CC / 4; c++) {
        float4 h = h4[c];
        const float4* w4 = (const float4*)sW + c;
        float4 a = w4[0], b = w4[32], d = w4[64], e = w4[96], f = w4[128];
        y0 += h.x * a.x + h.y * a.y + h.z * a.z + h.w * a.w;
        y1 += h.x * b.x + h.y * b.y + h.z * b.z + h.w * b.w;
        y2 += h.x * d.x + h.y * d.y + h.z * d.z + h.w * d.w;
        y3 += h.x * e.x + h.y * e.y + h.z * e.z + h.w * e.w;
        y4 += h.x * f.x + h.y * f.y + h.z * f.z + h.w * f.w;
    }
    float* yo = d_Y + g * DOUT;
    yo[0] = y0; yo[1] = y1; yo[2] = y2; yo[3] = y3; yo[4] = y4;
}

// ------------------------- K5: output BN + ReLU + transpose -----------------
__global__ void k_final(const float* __restrict__ g_out,
                        const float* __restrict__ be_out,
                        float* __restrict__ out) {
    int t = blockIdx.x, tid = threadIdx.x;
    float s1[DOUT], s2[DOUT];
    #pragma unroll
    for (int o = 0; o < DOUT; o++) { s1[o] = 0.f; s2[o] = 0.f; }
    for (int b = tid; b < BB; b += 256) {
        const float* y = d_Y + ((size_t)t * BB + b) * DOUT;
        #pragma unroll
        for (int o = 0; o < DOUT; o++) { float v = y[o]; s1[o] += v; s2[o] += v * v; }
    }
    __shared__ float r1[DOUT][256], r2[DOUT][256];
    #pragma unroll
    for (int o = 0; o < DOUT; o++) { r1[o][tid] = s1[o]; r2[o][tid] = s2[o]; }
    __syncthreads();
    for (int s = 128; s > 0; s >>= 1) {
        if (tid < s) {
            #pragma unroll
            for (int o = 0; o < DOUT; o++) {
                r1[o][tid] += r1[o][tid + s];
                r2[o][tid] += r2[o][tid + s];
            }
        }
        __syncthreads();
    }
    __shared__ float mu[DOUT], rs[DOUT], bb[DOUT];
    if (tid < DOUT) {
        float m = r1[tid][0] * (1.0f / BB);
        float v = r2[tid][0] * (1.0f / BB) - m * m;
        mu[tid] = m;
        rs[tid] = rsqrtf(v + EPSV) * g_out[tid];
        bb[tid] = be_out[tid];
    }
    __syncthreads();
    for (int b = tid; b < BB; b += 256) {
        const float* y = d_Y + ((size_t)t * BB + b) * DOUT;
        float* op = out + ((size_t)b * TT + t) * DOUT;
        #pragma unroll
        for (int o = 0; o < DOUT; o++)
            op[o] = fmaxf(fmaf(y[o] - mu[o], rs[o], bb[o]), 0.f);
    }
}

// ------------------------- launch -------------------------------------------
extern "C" void kernel_launch(void* const* d_in, const int* in_sizes, int n_in,
                              void* d_out, int out_size) {
    const float* inp    = (const float*)d_in[0];
    const float* W_emb  = (const float*)d_in[1];
    const float* b_emb  = (const float*)d_in[2];
    const float* g_emb  = (const float*)d_in[3];
    const float* be_emb = (const float*)d_in[4];
    const float* W_ih   = (const float*)d_in[5];
    const float* W_hh   = (const float*)d_in[6];
    const float* b_ih   = (const float*)d_in[7];
    const float* b_hh   = (const float*)d_in[8];
    const float* W_out  = (const float*)d_in[9];
    const float* b_out  = (const float*)d_in[10];
    const float* g_out  = (const float*)d_in[11];
    const float* be_out = (const float*)d_in[12];
    float* out = (float*)d_out;

    const int lstm_smem = (KTOT * SC_STR + 2 * WCH) * (int)sizeof(float); // 198656
    cudaFuncSetAttribute(k_lstm, cudaFuncAttributeMaxDynamicSharedMemorySize, lstm_smem);

    k_moments<<<TT, 256>>>(inp);
    k_prep<<<512, 256>>>(W_emb, b_emb, g_emb, be_emb, W_ih, W_hh, b_ih, b_hh);
    k_lstm<<<NCTA, 256, lstm_smem>>>(inp);
    k_out<<<(TT * BB) / 256, 256>>>(W_out, b_out);
    k_final<<<TT, 256>>>(g_out, be_out, out);
}

// round 9
// speedup vs baseline: 1.0728x; 1.0720x over previous
#include <cuda_runtime.h>
#include <cuda_bf16.h>
#include <cstdint>

#define BB 8192
#define TT 128
#define EE 128
#define CC 128
#define DOUT 5
#define BM 64
#define NCTA 128
#define EPSV 1e-5f
#define AST 264                      // A tile row stride (bf16 elems) = 528B
#define SGS 521                      // gates smem row stride (floats), odd: conflict-free
#define RING_OFF 67584               // ring / sG offset in dynamic smem
#define DSM_BYTES (RING_OFF + 64 * SGS * 4)   // 67584 + 133376 = 200960
#define SWZ(x) ((x) ^ (((x) >> 3) & 0x70))

__device__ float d_mom[TT * 5];
__device__ float d_A[TT * EE], d_Bc[TT * EE], d_Cc[TT * EE];
__device__ float d_bias[512];
__device__ __align__(256) __nv_bfloat16 d_Wb[8 * 32768];   // 8 chunks x 64KB (4 hi, 4 lo)
__device__ float d_H[(size_t)TT * BB * CC];
__device__ float d_Y[(size_t)TT * BB * DOUT];

__device__ __forceinline__ float sigm(float x) { return __fdividef(1.f, 1.f + __expf(-x)); }
__device__ __forceinline__ float tanh_f(float x) { return 1.f - __fdividef(2.f, __expf(2.f * x) + 1.f); }
__device__ __forceinline__ uint32_t s2u(const void* p) {
    uint32_t a;
    asm("{ .reg .u64 t; cvta.to.shared.u64 t, %1; cvt.u32.u64 %0, t; }" : "=r"(a) : "l"(p));
    return a;
}
#define CPA16(dst, src) \
    asm volatile("cp.async.cg.shared.global [%0], [%1], 16;" :: "r"(dst), "l"(src))
#define LDSM4(r, a) \
    asm volatile("ldmatrix.sync.aligned.m8n8.x4.shared.b16 {%0,%1,%2,%3}, [%4];" \
        : "=r"((r)[0]), "=r"((r)[1]), "=r"((r)[2]), "=r"((r)[3]) : "r"(a))
#define MMA16816(d, a, b0, b1) \
    asm volatile("mma.sync.aligned.m16n8k16.row.col.f32.bf16.bf16.f32 " \
        "{%0,%1,%2,%3}, {%4,%5,%6,%7}, {%8,%9}, {%0,%1,%2,%3};" \
        : "+f"((d)[0]), "+f"((d)[1]), "+f"((d)[2]), "+f"((d)[3]) \
        : "r"((a)[0]), "r"((a)[1]), "r"((a)[2]), "r"((a)[3]), "r"(b0), "r"(b1))

// ---------------- K1: per-t input moments ----------------
__global__ void k_moments(const float* __restrict__ inp) {
    int t = blockIdx.x, tid = threadIdx.x;
    float su = 0, sv = 0, suu = 0, svv = 0, suv = 0;
    for (int b = tid; b < BB; b += 256) {
        float2 uv = *(const float2*)(inp + ((size_t)b * TT + t) * 2);
        su += uv.x; sv += uv.y; suu += uv.x * uv.x; svv += uv.y * uv.y; suv += uv.x * uv.y;
    }
    __shared__ float red[5][256];
    red[0][tid] = su; red[1][tid] = sv; red[2][tid] = suu; red[3][tid] = svv; red[4][tid] = suv;
    __syncthreads();
    for (int s = 128; s > 0; s >>= 1) {
        if (tid < s)
            for (int m = 0; m < 5; m++) red[m][tid] += red[m][tid + s];
        __syncthreads();
    }
    if (tid < 5) d_mom[t * 5 + tid] = red[tid][0] * (1.0f / BB);
}

// ------- K2: BN coeffs + bias + bf16 hi/lo split swizzled weight chunks -----
// Chunk c (0..7): k rows (c&3)*64..+63; c<4 = hi part, c>=4 = lo residual.
// In-chunk layout [n=512][k=64] bf16, SW128-swizzled (bits[6:4]^=n&7).
__global__ void k_prep(const float* __restrict__ W_emb, const float* __restrict__ b_emb,
                       const float* __restrict__ g_emb, const float* __restrict__ be_emb,
                       const float* __restrict__ W_ih, const float* __restrict__ W_hh,
                       const float* __restrict__ b_ih, const float* __restrict__ b_hh) {
    int idx = blockIdx.x * 256 + threadIdx.x;   // grid covers 262144
    if (idx < 8 * 32768) {
        int c = idx >> 15, rem = idx & 32767;
        int n = rem >> 6, kl = rem & 63;
        int k_orig = (c & 3) * 64 + kl;
        float w = (k_orig < 128) ? W_ih[n * 128 + k_orig]
                                 : W_hh[n * 128 + (k_orig - 128)];
        __nv_bfloat16 hi = __float2bfloat16(w);
        __nv_bfloat16 v = (c >= 4) ? __float2bfloat16(w - __bfloat162float(hi)) : hi;
        *(__nv_bfloat16*)((char*)d_Wb + c * 65536 + SWZ((uint32_t)(n * 128 + kl * 2))) = v;
    }
    if (idx < 512) d_bias[idx] = b_ih[idx] + b_hh[idx];
    if (idx < TT * EE) {
        int t = idx >> 7, e = idx & 127;
        float w0 = W_emb[e * 2], w1 = W_emb[e * 2 + 1], bb = b_emb[e];
        float mu_u = d_mom[t * 5], mu_v = d_mom[t * 5 + 1];
        float vu = d_mom[t * 5 + 2] - mu_u * mu_u;
        float vv = d_mom[t * 5 + 3] - mu_v * mu_v;
        float cuv = d_mom[t * 5 + 4] - mu_u * mu_v;
        float mu = w0 * mu_u + w1 * mu_v + bb;
        float var = w0 * w0 * vu + w1 * w1 * vv + 2.f * w0 * w1 * cuv;
        float sc = g_emb[e] * rsqrtf(var + EPSV);
        d_A[idx] = sc * w0; d_Bc[idx] = sc * w1;
        d_Cc[idx] = sc * (bb - mu) + be_emb[e];
    }
}

// ---------------- K3: persistent mma.sync bf16 LSTM ----------------
// dyn smem: sAh [64 x 264] bf16 (33792B), sAl same, then ring 2x64KB
// (reused as sG[64][521] fp32 after the last chunk of each step).
__global__ void __launch_bounds__(256, 1)
k_lstm(const float* __restrict__ inp) {
    extern __shared__ char dsm[];
    __nv_bfloat16* sAh = (__nv_bfloat16*)dsm;
    __nv_bfloat16* sAl = (__nv_bfloat16*)(dsm + 33792);
    float* sG = (float*)(dsm + RING_OFF);
    const uint32_t dsmU = s2u(dsm);
    const uint32_t sAhU = dsmU, sAlU = dsmU + 33792, ringU = dsmU + RING_OFF;

    __shared__ float sBias[512];
    __shared__ float sAe[EE], sBe[EE], sCe[EE];
    __shared__ float sUV[BM * 2];

    const int tid = threadIdx.x, lane = tid & 31, wid = tid >> 5;
    const int b0 = blockIdx.x * BM;
    const int grp = lane >> 3, li = lane & 7;
    const int rowA = (grp & 1) * 8 + li;        // A ldmatrix row-in-tile
    const int kaddA = (grp >> 1) * 8;
    const int nB = ((grp >> 1) & 1) * 8 + li;   // B ldmatrix n-in-tile
    const int kaddB = (grp & 1) * 8;
    const int nbW = wid * 64;                   // this warp's N range

    for (int i = tid; i < 512; i += 256) sBias[i] = d_bias[i];
    for (int i = tid; i < 64 * 64; i += 256) {  // zero h region (cols 128..255)
        int r = i >> 6, cq = i & 63;
        *(uint32_t*)(sAh + r * AST + 128 + 2 * cq) = 0;
        *(uint32_t*)(sAl + r * AST + 128 + 2 * cq) = 0;
    }
    float cst[32];
    #pragma unroll
    for (int i = 0; i < 32; i++) cst[i] = 0.f;
    __syncthreads();

    for (int t = 0; t < TT; t++) {
        if (tid < BM) {
            float2 uv = *(const float2*)(inp + ((size_t)(b0 + tid) * TT + t) * 2);
            sUV[tid * 2] = uv.x; sUV[tid * 2 + 1] = uv.y;
        }
        if (tid < EE) {
            sAe[tid] = d_A[t * EE + tid];
            sBe[tid] = d_Bc[t * EE + tid];
            sCe[tid] = d_Cc[t * EE + tid];
        }
        __syncthreads();      // also: all sG readers of step t-1 are done

        // prologue: chunks 0,1 -> ring slots 0,1 (ring free again each step)
        #pragma unroll
        for (int pc = 0; pc < 2; pc++) {
            const char* src = (const char*)d_Wb + pc * 65536 + tid * 256;
            uint32_t dst = ringU + pc * 65536 + tid * 256;
            #pragma unroll
            for (int q = 0; q < 16; q++) CPA16(dst + q * 16, src + q * 16);
            asm volatile("cp.async.commit_group;");
        }

        // xbn -> A tiles cols 0..127 (hi + lo)
        for (int i = tid; i < 64 * 64; i += 256) {
            int r = i >> 6, ep = i & 63, e = 2 * ep;
            float u = sUV[2 * r], v = sUV[2 * r + 1];
            float x0 = fmaxf(fmaf(sAe[e], u, fmaf(sBe[e], v, sCe[e])), 0.f);
            float x1 = fmaxf(fmaf(sAe[e + 1], u, fmaf(sBe[e + 1], v, sCe[e + 1])), 0.f);
            __nv_bfloat16 h0 = __float2bfloat16(x0), h1 = __float2bfloat16(x1);
            __nv_bfloat162 hp; hp.x = h0; hp.y = h1;
            __nv_bfloat162 lp;
            lp.x = __float2bfloat16(x0 - __bfloat162float(h0));
            lp.y = __float2bfloat16(x1 - __bfloat162float(h1));
            *(__nv_bfloat162*)(sAh + r * AST + e) = hp;
            *(__nv_bfloat162*)(sAl + r * AST + e) = lp;
        }

        float acc[4][8][4];
        #pragma unroll
        for (int a = 0; a < 4; a++)
            #pragma unroll
            for (int b = 0; b < 8; b++)
                #pragma unroll
                for (int q = 0; q < 4; q++) acc[a][b][q] = 0.f;

        // 8 chunk passes: c<4 hi-weights (x2: A_hi then A_lo), c>=4 lo-weights (A_hi)
        for (int c = 0; c < 8; c++) {
            const int s = c & 1;
            if (c == 7) asm volatile("cp.async.wait_group 0;" ::: "memory");
            else        asm volatile("cp.async.wait_group 1;" ::: "memory");
            __syncthreads();            // chunk c visible to all; xbn writes visible
            const uint32_t slotU = ringU + s * 65536;
            const int kb = (c & 3) * 64;
            const int reps = (c < 4) ? 2 : 1;
            for (int rep = 0; rep < reps; rep++) {
                const uint32_t aBase = (rep == 1) ? sAlU : sAhU;
                #pragma unroll
                for (int ks = 0; ks < 4; ks++) {
                    const int kcol = kb + ks * 16;
                    uint32_t af[4][4];
                    #pragma unroll
                    for (int mi = 0; mi < 4; mi++) {
                        uint32_t ad = aBase +
                            (uint32_t)((mi * 16 + rowA) * AST + kcol + kaddA) * 2;
                        LDSM4(af[mi], ad);
                    }
                    #pragma unroll
                    for (int p = 0; p < 4; p++) {
                        uint32_t bfr[4];
                        uint32_t off = (uint32_t)((nbW + p * 16 + nB) * 128 +
                                                  (ks * 16 + kaddB) * 2);
                        LDSM4(bfr, slotU + SWZ(off));
                        #pragma unroll
                        for (int mi = 0; mi < 4; mi++) {
                            MMA16816(acc[mi][2 * p],     af[mi], bfr[0], bfr[1]);
                            MMA16816(acc[mi][2 * p + 1], af[mi], bfr[2], bfr[3]);
                        }
                    }
                }
            }
            __syncthreads();            // all warps done reading slot s
            if (c < 6) {                // refill slot s with chunk c+2
                const char* src = (const char*)d_Wb + (c + 2) * 65536 + tid * 256;
                uint32_t dst = ringU + s * 65536 + tid * 256;
                #pragma unroll
                for (int q = 0; q < 16; q++) CPA16(dst + q * 16, src + q * 16);
                asm volatile("cp.async.commit_group;");
            }
        }

        // gates fragments -> sG (reusing ring smem)
        {
            const int mrow = lane >> 2, ncol = nbW + 2 * (lane & 3);
            #pragma unroll
            for (int mi = 0; mi < 4; mi++)
                #pragma unroll
                for (int nj = 0; nj < 8; nj++) {
                    int m = mi * 16 + mrow, n = ncol + nj * 8;
                    sG[m * SGS + n]           = acc[mi][nj][0];
                    sG[m * SGS + n + 1]       = acc[mi][nj][1];
                    sG[(m + 8) * SGS + n]     = acc[mi][nj][2];
                    sG[(m + 8) * SGS + n + 1] = acc[mi][nj][3];
                }
        }
        __syncthreads();

        // cell update (R3-proven pattern): thread = (rowE, qE), 32 channels each
        {
            const int rowE = tid & 63, qE = tid >> 6;
            const float* grow = sG + rowE * SGS;
            float* Hrow = d_H + ((size_t)t * BB + b0 + rowE) * CC;
            #pragma unroll
            for (int j = 0; j < 32; j++) {
                int n = qE + 4 * j;
                float I = grow[n]       + sBias[n];
                float F = grow[128 + n] + sBias[128 + n];
                float G = grow[256 + n] + sBias[256 + n];
                float O = grow[384 + n] + sBias[384 + n];
                float cn = sigm(F) * cst[j] + sigm(I) * tanh_f(G);
                cst[j] = cn;
                float h = sigm(O) * tanh_f(cn);
                __nv_bfloat16 hh = __float2bfloat16(h);
                sAh[rowE * AST + 128 + n] = hh;
                sAl[rowE * AST + 128 + n] = __float2bfloat16(h - __bfloat162float(hh));
                Hrow[n] = h;
            }
        }
        __syncthreads();
    }
}

// ---------------- K4: output head y = h@Wout^T + b ----------------
__global__ void k_out(const float* __restrict__ W_out, const float* __restrict__ b_out) {
    __shared__ float sW[DOUT * CC];
    __shared__ float sb[DOUT];
    int tid = threadIdx.x;
    for (int i = tid; i < DOUT * CC; i += 256) sW[i] = W_out[i];
    if (tid < DOUT) sb[tid] = b_out[tid];
    __syncthreads();
    size_t g = (size_t)blockIdx.x * 256 + tid;
    const float4* h4 = (const float4*)(d_H + g * CC);
    float y0 = sb[0], y1 = sb[1], y2 = sb[2], y3 = sb[3], y4 = sb[4];
    #pragma unroll 8
    for (int c = 0; c < CC / 4; c++) {
        float4 h = h4[c];
        const float4* w4 = (const float4*)sW + c;
        float4 a = w4[0], b = w4[32], d = w4[64], e = w4[96], f = w4[128];
        y0 += h.x * a.x + h.y * a.y + h.z * a.z + h.w * a.w;
        y1 += h.x * b.x + h.y * b.y + h.z * b.z + h.w * b.w;
        y2 += h.x * d.x + h.y * d.y + h.z * d.z + h.w * d.w;
        y3 += h.x * e.x + h.y * e.y + h.z * e.z + h.w * e.w;
        y4 += h.x * f.x + h.y * f.y + h.z * f.z + h.w * f.w;
    }
    float* yo = d_Y + g * DOUT;
    yo[0] = y0; yo[1] = y1; yo[2] = y2; yo[3] = y3; yo[4] = y4;
}

// ---------------- K5: output BN + ReLU + transpose ----------------
__global__ void k_final(const float* __restrict__ g_out, const float* __restrict__ be_out,
                        float* __restrict__ out) {
    int t = blockIdx.x, tid = threadIdx.x;
    float s1[DOUT], s2[DOUT];
    #pragma unroll
    for (int o = 0; o < DOUT; o++) { s1[o] = 0.f; s2[o] = 0.f; }
    for (int b = tid; b < BB; b += 256) {
        const float* y = d_Y + ((size_t)t * BB + b) * DOUT;
        #pragma unroll
        for (int o = 0; o < DOUT; o++) { float v = y[o]; s1[o] += v; s2[o] += v * v; }
    }
    __shared__ float r1[DOUT][256], r2[DOUT][256];
    #pragma unroll
    for (int o = 0; o < DOUT; o++) { r1[o][tid] = s1[o]; r2[o][tid] = s2[o]; }
    __syncthreads();
    for (int s = 128; s > 0; s >>= 1) {
        if (tid < s)
            #pragma unroll
            for (int o = 0; o < DOUT; o++) {
                r1[o][tid] += r1[o][tid + s]; r2[o][tid] += r2[o][tid + s];
            }
        __syncthreads();
    }
    __shared__ float mu[DOUT], rs[DOUT], bb[DOUT];
    if (tid < DOUT) {
        float m = r1[tid][0] * (1.0f / BB);
        float v = r2[tid][0] * (1.0f / BB) - m * m;
        mu[tid] = m; rs[tid] = rsqrtf(v + EPSV) * g_out[tid]; bb[tid] = be_out[tid];
    }
    __syncthreads();
    for (int b = tid; b < BB; b += 256) {
        const float* y = d_Y + ((size_t)t * BB + b) * DOUT;
        float* op = out + ((size_t)b * TT + t) * DOUT;
        #pragma unroll
        for (int o = 0; o < DOUT; o++)
            op[o] = fmaxf(fmaf(y[o] - mu[o], rs[o], bb[o]), 0.f);
    }
}

extern "C" void kernel_launch(void* const* d_in, const int* in_sizes, int n_in,
                              void* d_out, int out_size) {
    const float* inp    = (const float*)d_in[0];
    const float* W_emb  = (const float*)d_in[1];
    const float* b_emb  = (const float*)d_in[2];
    const float* g_emb  = (const float*)d_in[3];
    const float* be_emb = (const float*)d_in[4];
    const float* W_ih   = (const float*)d_in[5];
    const float* W_hh   = (const float*)d_in[6];
    const float* b_ih   = (const float*)d_in[7];
    const float* b_hh   = (const float*)d_in[8];
    const float* W_out  = (const float*)d_in[9];
    const float* b_out  = (const float*)d_in[10];
    const float* g_out  = (const float*)d_in[11];
    const float* be_out = (const float*)d_in[12];
    float* out = (float*)d_out;

    cudaFuncSetAttribute(k_lstm, cudaFuncAttributeMaxDynamicSharedMemorySize, DSM_BYTES);

    k_moments<<<TT, 256>>>(inp);
    k_prep<<<1024, 256>>>(W_emb, b_emb, g_emb, be_emb, W_ih, W_hh, b_ih, b_hh);
    k_lstm<<<NCTA, 256, DSM_BYTES>>>(inp);
    k_out<<<(TT * BB) / 256, 256>>>(W_out, b_out);
    k_final<<<TT, 256>>>(g_out, be_out, out);
}

// round 10
// speedup vs baseline: 1.0736x; 1.0008x over previous
#include <cuda_runtime.h>
#include <cuda_bf16.h>
#include <cstdint>

#define BB 8192
#define TT 128
#define EE 128
#define CC 128
#define DOUT 5
#define BM 64
#define NCTA 128
#define EPSV 1e-5f
#define AST 264                      // A tile row stride (bf16 elems) = 528B
#define SGS 521                      // gates smem row stride (floats), odd: conflict-free
#define RING_OFF 67584               // ring / sG offset in dynamic smem
#define DSM_BYTES (RING_OFF + 64 * SGS * 4)   // 67584 + 133376 = 200960
#define SWZ(x) ((x) ^ (((x) >> 3) & 0x70))

__device__ float d_mom[TT * 5];
__device__ float d_A[TT * EE], d_Bc[TT * EE], d_Cc[TT * EE];
__device__ float d_bias[512];
__device__ __align__(256) __nv_bfloat16 d_Wb[8 * 32768];   // 8 chunks x 64KB (4 hi, 4 lo)
__device__ float d_H[(size_t)TT * BB * CC];
__device__ float d_Y[(size_t)TT * BB * DOUT];

__device__ __forceinline__ float sigm(float x) { return __fdividef(1.f, 1.f + __expf(-x)); }
__device__ __forceinline__ float tanh_f(float x) { return 1.f - __fdividef(2.f, __expf(2.f * x) + 1.f); }
__device__ __forceinline__ uint32_t s2u(const void* p) {
    uint32_t a;
    asm("{ .reg .u64 t; cvta.to.shared.u64 t, %1; cvt.u32.u64 %0, t; }" : "=r"(a) : "l"(p));
    return a;
}
#define CPA16(dst, src) \
    asm volatile("cp.async.cg.shared.global [%0], [%1], 16;" :: "r"(dst), "l"(src))
#define LDSM4(r, a) \
    asm volatile("ldmatrix.sync.aligned.m8n8.x4.shared.b16 {%0,%1,%2,%3}, [%4];" \
        : "=r"((r)[0]), "=r"((r)[1]), "=r"((r)[2]), "=r"((r)[3]) : "r"(a))
#define MMA16816(d, a, b0, b1) \
    asm volatile("mma.sync.aligned.m16n8k16.row.col.f32.bf16.bf16.f32 " \
        "{%0,%1,%2,%3}, {%4,%5,%6,%7}, {%8,%9}, {%0,%1,%2,%3};" \
        : "+f"((d)[0]), "+f"((d)[1]), "+f"((d)[2]), "+f"((d)[3]) \
        : "r"((a)[0]), "r"((a)[1]), "r"((a)[2]), "r"((a)[3]), "r"(b0), "r"(b1))

// ---------------- K1: per-t input moments ----------------
__global__ void k_moments(const float* __restrict__ inp) {
    int t = blockIdx.x, tid = threadIdx.x;
    float su = 0, sv = 0, suu = 0, svv = 0, suv = 0;
    for (int b = tid; b < BB; b += 256) {
        float2 uv = *(const float2*)(inp + ((size_t)b * TT + t) * 2);
        su += uv.x; sv += uv.y; suu += uv.x * uv.x; svv += uv.y * uv.y; suv += uv.x * uv.y;
    }
    __shared__ float red[5][256];
    red[0][tid] = su; red[1][tid] = sv; red[2][tid] = suu; red[3][tid] = svv; red[4][tid] = suv;
    __syncthreads();
    for (int s = 128; s > 0; s >>= 1) {
        if (tid < s)
            for (int m = 0; m < 5; m++) red[m][tid] += red[m][tid + s];
        __syncthreads();
    }
    if (tid < 5) d_mom[t * 5 + tid] = red[tid][0] * (1.0f / BB);
}

// ------- K2: BN coeffs + bias + bf16 hi/lo split swizzled weight chunks -----
// Chunk c (0..7): k rows (c&3)*64..+63; c<4 = hi part, c>=4 = lo residual.
// In-chunk layout [n=512][k=64] bf16, SW128-swizzled (bits[6:4]^=n&7).
__global__ void k_prep(const float* __restrict__ W_emb, const float* __restrict__ b_emb,
                       const float* __restrict__ g_emb, const float* __restrict__ be_emb,
                       const float* __restrict__ W_ih, const float* __restrict__ W_hh,
                       const float* __restrict__ b_ih, const float* __restrict__ b_hh) {
    int idx = blockIdx.x * 256 + threadIdx.x;   // grid covers 262144
    if (idx < 8 * 32768) {
        int c = idx >> 15, rem = idx & 32767;
        int n = rem >> 6, kl = rem & 63;
        int k_orig = (c & 3) * 64 + kl;
        float w = (k_orig < 128) ? W_ih[n * 128 + k_orig]
                                 : W_hh[n * 128 + (k_orig - 128)];
        __nv_bfloat16 hi = __float2bfloat16(w);
        __nv_bfloat16 v = (c >= 4) ? __float2bfloat16(w - __bfloat162float(hi)) : hi;
        *(__nv_bfloat16*)((char*)d_Wb + c * 65536 + SWZ((uint32_t)(n * 128 + kl * 2))) = v;
    }
    if (idx < 512) d_bias[idx] = b_ih[idx] + b_hh[idx];
    if (idx < TT * EE) {
        int t = idx >> 7, e = idx & 127;
        float w0 = W_emb[e * 2], w1 = W_emb[e * 2 + 1], bb = b_emb[e];
        float mu_u = d_mom[t * 5], mu_v = d_mom[t * 5 + 1];
        float vu = d_mom[t * 5 + 2] - mu_u * mu_u;
        float vv = d_mom[t * 5 + 3] - mu_v * mu_v;
        float cuv = d_mom[t * 5 + 4] - mu_u * mu_v;
        float mu = w0 * mu_u + w1 * mu_v + bb;
        float var = w0 * w0 * vu + w1 * w1 * vv + 2.f * w0 * w1 * cuv;
        float sc = g_emb[e] * rsqrtf(var + EPSV);
        d_A[idx] = sc * w0; d_Bc[idx] = sc * w1;
        d_Cc[idx] = sc * (bb - mu) + be_emb[e];
    }
}

// ---------------- K3: persistent mma.sync bf16 LSTM ----------------
// dyn smem: sAh [64 x 264] bf16 (33792B), sAl same, then ring 2x64KB
// (reused as sG[64][521] fp32 after the last chunk of each step).
__global__ void __launch_bounds__(256, 1)
k_lstm(const float* __restrict__ inp) {
    extern __shared__ char dsm[];
    __nv_bfloat16* sAh = (__nv_bfloat16*)dsm;
    __nv_bfloat16* sAl = (__nv_bfloat16*)(dsm + 33792);
    float* sG = (float*)(dsm + RING_OFF);
    const uint32_t dsmU = s2u(dsm);
    const uint32_t sAhU = dsmU, sAlU = dsmU + 33792, ringU = dsmU + RING_OFF;

    __shared__ float sBias[512];
    __shared__ float sAe[EE], sBe[EE], sCe[EE];
    __shared__ float sUV[BM * 2];

    const int tid = threadIdx.x, lane = tid & 31, wid = tid >> 5;
    const int b0 = blockIdx.x * BM;
    const int grp = lane >> 3, li = lane & 7;
    const int rowA = (grp & 1) * 8 + li;        // A ldmatrix row-in-tile
    const int kaddA = (grp >> 1) * 8;
    const int nB = ((grp >> 1) & 1) * 8 + li;   // B ldmatrix n-in-tile
    const int kaddB = (grp & 1) * 8;
    const int nbW = wid * 64;                   // this warp's N range

    for (int i = tid; i < 512; i += 256) sBias[i] = d_bias[i];
    for (int i = tid; i < 64 * 64; i += 256) {  // zero h region (cols 128..255)
        int r = i >> 6, cq = i & 63;
        *(uint32_t*)(sAh + r * AST + 128 + 2 * cq) = 0;
        *(uint32_t*)(sAl + r * AST + 128 + 2 * cq) = 0;
    }
    float cst[32];
    #pragma unroll
    for (int i = 0; i < 32; i++) cst[i] = 0.f;
    __syncthreads();

    for (int t = 0; t < TT; t++) {
        if (tid < BM) {
            float2 uv = *(const float2*)(inp + ((size_t)(b0 + tid) * TT + t) * 2);
            sUV[tid * 2] = uv.x; sUV[tid * 2 + 1] = uv.y;
        }
        if (tid < EE) {
            sAe[tid] = d_A[t * EE + tid];
            sBe[tid] = d_Bc[t * EE + tid];
            sCe[tid] = d_Cc[t * EE + tid];
        }
        __syncthreads();      // also: all sG readers of step t-1 are done

        // prologue: chunks 0,1 -> ring slots 0,1 (ring free again each step)
        #pragma unroll
        for (int pc = 0; pc < 2; pc++) {
            const char* src = (const char*)d_Wb + pc * 65536 + tid * 256;
            uint32_t dst = ringU + pc * 65536 + tid * 256;
            #pragma unroll
            for (int q = 0; q < 16; q++) CPA16(dst + q * 16, src + q * 16);
            asm volatile("cp.async.commit_group;");
        }

        // xbn -> A tiles cols 0..127 (hi + lo)
        for (int i = tid; i < 64 * 64; i += 256) {
            int r = i >> 6, ep = i & 63, e = 2 * ep;
            float u = sUV[2 * r], v = sUV[2 * r + 1];
            float x0 = fmaxf(fmaf(sAe[e], u, fmaf(sBe[e], v, sCe[e])), 0.f);
            float x1 = fmaxf(fmaf(sAe[e + 1], u, fmaf(sBe[e + 1], v, sCe[e + 1])), 0.f);
            __nv_bfloat16 h0 = __float2bfloat16(x0), h1 = __float2bfloat16(x1);
            __nv_bfloat162 hp; hp.x = h0; hp.y = h1;
            __nv_bfloat162 lp;
            lp.x = __float2bfloat16(x0 - __bfloat162float(h0));
            lp.y = __float2bfloat16(x1 - __bfloat162float(h1));
            *(__nv_bfloat162*)(sAh + r * AST + e) = hp;
            *(__nv_bfloat162*)(sAl + r * AST + e) = lp;
        }

        float acc[4][8][4];
        #pragma unroll
        for (int a = 0; a < 4; a++)
            #pragma unroll
            for (int b = 0; b < 8; b++)
                #pragma unroll
                for (int q = 0; q < 4; q++) acc[a][b][q] = 0.f;

        // 8 chunk passes: c<4 hi-weights (x2: A_hi then A_lo), c>=4 lo-weights (A_hi)
        for (int c = 0; c < 8; c++) {
            const int s = c & 1;
            if (c == 7) asm volatile("cp.async.wait_group 0;" ::: "memory");
            else        asm volatile("cp.async.wait_group 1;" ::: "memory");
            __syncthreads();            // chunk c visible to all; xbn writes visible
            const uint32_t slotU = ringU + s * 65536;
            const int kb = (c & 3) * 64;
            const int reps = (c < 4) ? 2 : 1;
            for (int rep = 0; rep < reps; rep++) {
                const uint32_t aBase = (rep == 1) ? sAlU : sAhU;
                #pragma unroll
                for (int ks = 0; ks < 4; ks++) {
                    const int kcol = kb + ks * 16;
                    uint32_t af[4][4];
                    #pragma unroll
                    for (int mi = 0; mi < 4; mi++) {
                        uint32_t ad = aBase +
                            (uint32_t)((mi * 16 + rowA) * AST + kcol + kaddA) * 2;
                        LDSM4(af[mi], ad);
                    }
                    #pragma unroll
                    for (int p = 0; p < 4; p++) {
                        uint32_t bfr[4];
                        uint32_t off = (uint32_t)((nbW + p * 16 + nB) * 128 +
                                                  (ks * 16 + kaddB) * 2);
                        LDSM4(bfr, slotU + SWZ(off));
                        #pragma unroll
                        for (int mi = 0; mi < 4; mi++) {
                            MMA16816(acc[mi][2 * p],     af[mi], bfr[0], bfr[1]);
                            MMA16816(acc[mi][2 * p + 1], af[mi], bfr[2], bfr[3]);
                        }
                    }
                }
            }
            __syncthreads();            // all warps done reading slot s
            if (c < 6) {                // refill slot s with chunk c+2
                const char* src = (const char*)d_Wb + (c + 2) * 65536 + tid * 256;
                uint32_t dst = ringU + s * 65536 + tid * 256;
                #pragma unroll
                for (int q = 0; q < 16; q++) CPA16(dst + q * 16, src + q * 16);
                asm volatile("cp.async.commit_group;");
            }
        }

        // gates fragments -> sG (reusing ring smem)
        {
            const int mrow = lane >> 2, ncol = nbW + 2 * (lane & 3);
            #pragma unroll
            for (int mi = 0; mi < 4; mi++)
                #pragma unroll
                for (int nj = 0; nj < 8; nj++) {
                    int m = mi * 16 + mrow, n = ncol + nj * 8;
                    sG[m * SGS + n]           = acc[mi][nj][0];
                    sG[m * SGS + n + 1]       = acc[mi][nj][1];
                    sG[(m + 8) * SGS + n]     = acc[mi][nj][2];
                    sG[(m + 8) * SGS + n + 1] = acc[mi][nj][3];
                }
        }
        __syncthreads();

        // cell update (R3-proven pattern): thread = (rowE, qE), 32 channels each
        {
            const int rowE = tid & 63, qE = tid >> 6;
            const float* grow = sG + rowE * SGS;
            float* Hrow = d_H + ((size_t)t * BB + b0 + rowE) * CC;
            #pragma unroll
            for (int j = 0; j < 32; j++) {
                int n = qE + 4 * j;
                float I = grow[n]       + sBias[n];
                float F = grow[128 + n] + sBias[128 + n];
                float G = grow[256 + n] + sBias[256 + n];
                float O = grow[384 + n] + sBias[384 + n];
                float cn = sigm(F) * cst[j] + sigm(I) * tanh_f(G);
                cst[j] = cn;
                float h = sigm(O) * tanh_f(cn);
                __nv_bfloat16 hh = __float2bfloat16(h);
                sAh[rowE * AST + 128 + n] = hh;
                sAl[rowE * AST + 128 + n] = __float2bfloat16(h - __bfloat162float(hh));
                Hrow[n] = h;
            }
        }
        __syncthreads();
    }
}

// ---------------- K4: output head y = h@Wout^T + b ----------------
__global__ void k_out(const float* __restrict__ W_out, const float* __restrict__ b_out) {
    __shared__ float sW[DOUT * CC];
    __shared__ float sb[DOUT];
    int tid = threadIdx.x;
    for (int i = tid; i < DOUT * CC; i += 256) sW[i] = W_out[i];
    if (tid < DOUT) sb[tid] = b_out[tid];
    __syncthreads();
    size_t g = (size_t)blockIdx.x * 256 + tid;
    const float4* h4 = (const float4*)(d_H + g * CC);
    float y0 = sb[0], y1 = sb[1], y2 = sb[2], y3 = sb[3], y4 = sb[4];
    #pragma unroll 8
    for (int c = 0; c < CC / 4; c++) {
        float4 h = h4[c];
        const float4* w4 = (const float4*)sW + c;
        float4 a = w4[0], b = w4[32], d = w4[64], e = w4[96], f = w4[128];
        y0 += h.x * a.x + h.y * a.y + h.z * a.z + h.w * a.w;
        y1 += h.x * b.x + h.y * b.y + h.z * b.z + h.w * b.w;
        y2 += h.x * d.x + h.y * d.y + h.z * d.z + h.w * d.w;
        y3 += h.x * e.x + h.y * e.y + h.z * e.z + h.w * e.w;
        y4 += h.x * f.x + h.y * f.y + h.z * f.z + h.w * f.w;
    }
    float* yo = d_Y + g * DOUT;
    yo[0] = y0; yo[1] = y1; yo[2] = y2; yo[3] = y3; yo[4] = y4;
}

// ---------------- K5: output BN + ReLU + transpose ----------------
__global__ void k_final(const float* __restrict__ g_out, const float* __restrict__ be_out,
                        float* __restrict__ out) {
    int t = blockIdx.x, tid = threadIdx.x;
    float s1[DOUT], s2[DOUT];
    #pragma unroll
    for (int o = 0; o < DOUT; o++) { s1[o] = 0.f; s2[o] = 0.f; }
    for (int b = tid; b < BB; b += 256) {
        const float* y = d_Y + ((size_t)t * BB + b) * DOUT;
        #pragma unroll
        for (int o = 0; o < DOUT; o++) { float v = y[o]; s1[o] += v; s2[o] += v * v; }
    }
    __shared__ float r1[DOUT][256], r2[DOUT][256];
    #pragma unroll
    for (int o = 0; o < DOUT; o++) { r1[o][tid] = s1[o]; r2[o][tid] = s2[o]; }
    __syncthreads();
    for (int s = 128; s > 0; s >>= 1) {
        if (tid < s)
            #pragma unroll
            for (int o = 0; o < DOUT; o++) {
                r1[o][tid] += r1[o][tid + s]; r2[o][tid] += r2[o][tid + s];
            }
        __syncthreads();
    }
    __shared__ float mu[DOUT], rs[DOUT], bb[DOUT];
    if (tid < DOUT) {
        float m = r1[tid][0] * (1.0f / BB);
        float v = r2[tid][0] * (1.0f / BB) - m * m;
        mu[tid] = m; rs[tid] = rsqrtf(v + EPSV) * g_out[tid]; bb[tid] = be_out[tid];
    }
    __syncthreads();
    for (int b = tid; b < BB; b += 256) {
        const float* y = d_Y + ((size_t)t * BB + b) * DOUT;
        float* op = out + ((size_t)b * TT + t) * DOUT;
        #pragma unroll
        for (int o = 0; o < DOUT; o++)
            op[o] = fmaxf(fmaf(y[o] - mu[o], rs[o], bb[o]), 0.f);
    }
}

extern "C" void kernel_launch(void* const* d_in, const int* in_sizes, int n_in,
                              void* d_out, int out_size) {
    const float* inp    = (const float*)d_in[0];
    const float* W_emb  = (const float*)d_in[1];
    const float* b_emb  = (const float*)d_in[2];
    const float* g_emb  = (const float*)d_in[3];
    const float* be_emb = (const float*)d_in[4];
    const float* W_ih   = (const float*)d_in[5];
    const float* W_hh   = (const float*)d_in[6];
    const float* b_ih   = (const float*)d_in[7];
    const float* b_hh   = (const float*)d_in[8];
    const float* W_out  = (const float*)d_in[9];
    const float* b_out  = (const float*)d_in[10];
    const float* g_out  = (const float*)d_in[11];
    const float* be_out = (const float*)d_in[12];
    float* out = (float*)d_out;

    cudaFuncSetAttribute(k_lstm, cudaFuncAttributeMaxDynamicSharedMemorySize, DSM_BYTES);

    k_moments<<<TT, 256>>>(inp);
    k_prep<<<1024, 256>>>(W_emb, b_emb, g_emb, be_emb, W_ih, W_hh, b_ih, b_hh);
    k_lstm<<<NCTA, 256, DSM_BYTES>>>(inp);
    k_out<<<(TT * BB) / 256, 256>>>(W_out, b_out);
    k_final<<<TT, 256>>>(g_out, be_out, out);
}

// round 12
// speedup vs baseline: 1.1116x; 1.0353x over previous
#include <cuda_runtime.h>
#include <cuda_bf16.h>
#include <cstdint>

#define BB 8192
#define TT 128
#define EE 128
#define CC 128
#define DOUT 5
#define BM 64
#define NCTA 128
#define EPSV 1e-5f
#define AST 264
#define AFS 68
#define OFF_AL 33792
#define OFF_AF 67584
#define OFF_RT 137216
#define OFF_RF 169984
#define DSM_REQ 203776
#define SWZ64(x) ((x) ^ (((x) >> 3) & 0x30))

__device__ float d_mom[TT * 5];
__device__ float d_A[TT * EE], d_Bc[TT * EE], d_Cc[TT * EE];
__device__ float d_bias[512];
__device__ __align__(256) __nv_bfloat16 d_WT[16 * 8192]; // [n256][k32] SW64, 16x16KB
__device__ __align__(256) float d_WF[256 * 256];         // [k][fcol]
__device__ float d_H[(size_t)TT * BB * CC];
__device__ float d_Y[(size_t)TT * BB * DOUT];

typedef unsigned long long ull;

__device__ __forceinline__ float sigm(float x) { return __fdividef(1.f, 1.f + __expf(-x)); }
__device__ __forceinline__ float tanh_f(float x) { return 1.f - __fdividef(2.f, __expf(2.f * x) + 1.f); }
__device__ __forceinline__ uint32_t s2u(const void* p) {
    uint32_t a;
    asm("{ .reg .u64 t; cvta.to.shared.u64 t, %1; cvt.u32.u64 %0, t; }" : "=r"(a) : "l"(p));
    return a;
}
__device__ __forceinline__ void ffma2(ull& d, ull a, ull b) {
    asm("fma.rn.f32x2 %0, %1, %2, %0;" : "+l"(d) : "l"(a), "l"(b));
}
__device__ __forceinline__ ull dup2(float x) {
    ull r; unsigned xi = __float_as_uint(x);
    asm("mov.b64 %0, {%1, %1};" : "=l"(r) : "r"(xi));
    return r;
}
__device__ __forceinline__ float2 unpk(ull v) {
    float2 r; asm("mov.b64 {%0, %1}, %2;" : "=f"(r.x), "=f"(r.y) : "l"(v));
    return r;
}
#define CPA16(dst, src) \
    asm volatile("cp.async.cg.shared.global [%0], [%1], 16;" :: "r"(dst), "l"(src))
#define LDSM4(r, a) \
    asm volatile("ldmatrix.sync.aligned.m8n8.x4.shared.b16 {%0,%1,%2,%3}, [%4];" \
        : "=r"((r)[0]), "=r"((r)[1]), "=r"((r)[2]), "=r"((r)[3]) : "r"(a))
#define MMA16816(d, a, b0, b1) \
    asm volatile("mma.sync.aligned.m16n8k16.row.col.f32.bf16.bf16.f32 " \
        "{%0,%1,%2,%3}, {%4,%5,%6,%7}, {%8,%9}, {%0,%1,%2,%3};" \
        : "+f"((d)[0]), "+f"((d)[1]), "+f"((d)[2]), "+f"((d)[3]) \
        : "r"((a)[0]), "r"((a)[1]), "r"((a)[2]), "r"((a)[3]), "r"(b0), "r"(b1))
#define BAR_T()   asm volatile("bar.sync 1, 256;" ::: "memory")
#define BAR_F()   asm volatile("bar.sync 2, 256;" ::: "memory")
#define BAR_ALL() asm volatile("bar.sync 3, 512;" ::: "memory")
#define WAITG1()  asm volatile("cp.async.wait_group 1;" ::: "memory")
#define COMMIT()  asm volatile("cp.async.commit_group;")

__device__ __constant__ int ordT[16] = {4,5,6,7,12,13,14,15,0,1,2,3,8,9,10,11};
__device__ __constant__ int ordF[16] = {8,9,10,11,12,13,14,15,0,1,2,3,4,5,6,7};

__global__ void k_moments(const float* __restrict__ inp) {
    int t = blockIdx.x, tid = threadIdx.x;
    float su = 0, sv = 0, suu = 0, svv = 0, suv = 0;
    for (int b = tid; b < BB; b += 256) {
        float2 uv = *(const float2*)(inp + ((size_t)b * TT + t) * 2);
        su += uv.x; sv += uv.y; suu += uv.x * uv.x; svv += uv.y * uv.y; suv += uv.x * uv.y;
    }
    __shared__ float red[5][256];
    red[0][tid] = su; red[1][tid] = sv; red[2][tid] = suu; red[3][tid] = svv; red[4][tid] = suv;
    __syncthreads();
    for (int s = 128; s > 0; s >>= 1) {
        if (tid < s)
            for (int m = 0; m < 5; m++) red[m][tid] += red[m][tid + s];
        __syncthreads();
    }
    if (tid < 5) d_mom[t * 5 + tid] = red[tid][0] * (1.0f / BB);
}

// d_WT chunk c: kb=(c&7)*32, c>=8 => lo residual; n = gate*64+ch (ch 0..63).
// d_WF: [k][fc], fc = gate*64+chL (orig channel 64+chL), chunk = 16 k-rows.
__global__ void k_prep(const float* __restrict__ W_emb, const float* __restrict__ b_emb,
                       const float* __restrict__ g_emb, const float* __restrict__ be_emb,
                       const float* __restrict__ W_ih, const float* __restrict__ W_hh,
                       const float* __restrict__ b_ih, const float* __restrict__ b_hh) {
    int idx = blockIdx.x * 256 + threadIdx.x;   // grid 512 blocks -> 131072
    if (idx < 131072) {
        int c = idx >> 13, rem = idx & 8191;
        int n = rem >> 5, kl = rem & 31;
        int k_orig = (c & 7) * 32 + kl;
        int row = (n >> 6) * 128 + (n & 63);
        float w = (k_orig < 128) ? W_ih[row * 128 + k_orig]
                                 : W_hh[row * 128 + (k_orig - 128)];
        __nv_bfloat16 hi = __float2bfloat16(w);
        __nv_bfloat16 v = (c >= 8) ? __float2bfloat16(w - __bfloat162float(hi)) : hi;
        *(__nv_bfloat16*)((char*)d_WT + c * 16384 + SWZ64((uint32_t)(n * 64 + kl * 2))) = v;
    }
    if (idx < 65536) {
        int k = idx >> 8, fc = idx & 255;
        int row = (fc >> 6) * 128 + 64 + (fc & 63);
        d_WF[k * 256 + fc] = (k < 128) ? W_ih[row * 128 + k] : W_hh[row * 128 + (k - 128)];
    }
    if (idx < 512) d_bias[idx] = b_ih[idx] + b_hh[idx];
    if (idx < TT * EE) {
        int t = idx >> 7, e = idx & 127;
        float w0 = W_emb[e * 2], w1 = W_emb[e * 2 + 1], bb = b_emb[e];
        float mu_u = d_mom[t * 5], mu_v = d_mom[t * 5 + 1];
        float vu = d_mom[t * 5 + 2] - mu_u * mu_u;
        float vv = d_mom[t * 5 + 3] - mu_v * mu_v;
        float cuv = d_mom[t * 5 + 4] - mu_u * mu_v;
        float mu = w0 * mu_u + w1 * mu_v + bb;
        float var = w0 * w0 * vu + w1 * w1 * vv + 2.f * w0 * w1 * cuv;
        float sc = g_emb[e] * rsqrtf(var + EPSV);
        d_A[idx] = sc * w0; d_Bc[idx] = sc * w1;
        d_Cc[idx] = sc * (bb - mu) + be_emb[e];
    }
}

__global__ void __launch_bounds__(512, 1)
k_lstm(const float* __restrict__ inp) {
    extern __shared__ char dsm_raw[];
    const uint32_t rawU = s2u(dsm_raw);
    const uint32_t base = (rawU + 1023) & ~1023u;
    char* dsm = dsm_raw + (base - rawU);
    __nv_bfloat16* sAh = (__nv_bfloat16*)dsm;
    __nv_bfloat16* sAl = (__nv_bfloat16*)(dsm + OFF_AL);
    float* sAf = (float*)(dsm + OFF_AF);
    const uint32_t AhU = base, AlU = base + OFF_AL;
    const uint32_t rTU = base + OFF_RT, rFU = base + OFF_RF;

    __shared__ float sBias[512];
    __shared__ float sAe[EE], sBe[EE], sCe[EE];
    __shared__ float sUV[BM * 2];

    const int tid = threadIdx.x, lane = tid & 31, wid = tid >> 5;
    const int b0 = blockIdx.x * BM;
    const bool isT = (wid & 4) == 0;
    const int eidx = (wid & 3) + ((wid >> 3) << 2);   // engine-local warp 0..7
    const int eTid = eidx * 32 + lane;
    const int grp = lane >> 3, li = lane & 7;
    const int rowA = (grp & 1) * 8 + li;
    const int kaddA = (grp >> 1) * 8;

    if (tid < 512) sBias[tid] = d_bias[tid];
    for (int i = tid; i < 4096; i += 512) {           // zero h region (bf16 tiles)
        int r = i >> 6, q = i & 63;
        *(uint32_t*)(sAh + r * AST + 128 + 2 * q) = 0;
        *(uint32_t*)(sAl + r * AST + 128 + 2 * q) = 0;
    }
    for (int i = tid; i < 256 * AFS; i += 512) sAf[i] = 0.f;
    __syncthreads();

    // prologue: each engine stages its first two chunks
    {
        const char* wsrc = isT ? (const char*)d_WT : (const char*)d_WF;
        const int* ord = isT ? ordT : ordF;
        uint32_t ring = isT ? rTU : rFU;
        #pragma unroll
        for (int pc = 0; pc < 2; pc++) {
            const char* src = wsrc + ord[pc] * 16384 + eTid * 64;
            uint32_t dst = ring + pc * 16384 + eTid * 64;
            #pragma unroll
            for (int q = 0; q < 4; q++) CPA16(dst + q * 16, src + q * 16);
            COMMIT();
        }
    }

    float cst[16];
    #pragma unroll
    for (int i = 0; i < 16; i++) cst[i] = 0.f;

    for (int t = 0; t < TT; t++) {
        if (tid < BM) {
            float2 uv = *(const float2*)(inp + ((size_t)(b0 + tid) * TT + t) * 2);
            sUV[tid * 2] = uv.x; sUV[tid * 2 + 1] = uv.y;
        }
        if (tid < EE) {
            sAe[tid] = d_A[t * EE + tid];
            sBe[tid] = d_Bc[t * EE + tid];
            sCe[tid] = d_Cc[t * EE + tid];
        }
        __syncthreads();

        // xbn -> A cols 0..127: bf16 hi/lo [row][k] + fp32 [k][row]
        for (int i = tid; i < 64 * 64; i += 512) {
            int r = i >> 6, ep = i & 63, e = 2 * ep;
            float u = sUV[2 * r], v = sUV[2 * r + 1];
            float x0 = fmaxf(fmaf(sAe[e], u, fmaf(sBe[e], v, sCe[e])), 0.f);
            float x1 = fmaxf(fmaf(sAe[e + 1], u, fmaf(sBe[e + 1], v, sCe[e + 1])), 0.f);
            __nv_bfloat16 h0 = __float2bfloat16(x0), h1 = __float2bfloat16(x1);
            __nv_bfloat162 hp; hp.x = h0; hp.y = h1;
            __nv_bfloat162 lp;
            lp.x = __float2bfloat16(x0 - __bfloat162float(h0));
            lp.y = __float2bfloat16(x1 - __bfloat162float(h1));
            *(__nv_bfloat162*)(sAh + r * AST + e) = hp;
            *(__nv_bfloat162*)(sAl + r * AST + e) = lp;
            sAf[e * AFS + r] = x0;
            sAf[(e + 1) * AFS + r] = x1;
        }
        __syncthreads();

        if (isT) {
            // ---- TENSOR engine: channels 0..63, 3-split bf16 ----
            float acc[4][4][4];
            #pragma unroll
            for (int a = 0; a < 4; a++)
                #pragma unroll
                for (int g = 0; g < 4; g++)
                    #pragma unroll
                    for (int q = 0; q < 4; q++) acc[a][g][q] = 0.f;

            for (int c = 0; c < 16; c++) {
                if (c == 8) BAR_ALL();
                WAITG1();
                BAR_T();
                const int ch = ordT[c];
                const uint32_t slotU = rTU + (c & 1) * 16384;
                uint32_t bfr[4][4];
                #pragma unroll
                for (int g = 0; g < 4; g++) {
                    uint32_t nrow = (uint32_t)(g * 64 + eidx * 8 + li);
                    LDSM4(bfr[g], slotU + SWZ64(nrow * 64 + (uint32_t)grp * 16));
                }
                const int kb = (ch & 7) * 32;
                const int reps = (ch < 8) ? 2 : 1;
                for (int rep = 0; rep < reps; rep++) {
                    const uint32_t aU = (rep == 1) ? AlU : AhU;
                    #pragma unroll
                    for (int ks = 0; ks < 2; ks++)
                        #pragma unroll
                        for (int mi = 0; mi < 4; mi++) {
                            uint32_t af[4];
                            LDSM4(af, aU + (uint32_t)((mi * 16 + rowA) * AST +
                                                      kb + ks * 16 + kaddA) * 2);
                            #pragma unroll
                            for (int g = 0; g < 4; g++)
                                MMA16816(acc[mi][g], af, bfr[g][2 * ks], bfr[g][2 * ks + 1]);
                        }
                }
                BAR_T();
                const char* src = (const char*)d_WT + ordT[(c + 2) & 15] * 16384 + eTid * 64;
                uint32_t dst = rTU + (c & 1) * 16384 + eTid * 64;
                #pragma unroll
                for (int q = 0; q < 4; q++) CPA16(dst + q * 16, src + q * 16);
                COMMIT();
            }
            // T cell update: ch pair chG..+1, rows mi*16+(lane>>2)+8*hf
            const int chG = eidx * 8 + 2 * (lane & 3);
            const float bi0 = sBias[chG],       bi1 = sBias[chG + 1];
            const float bf0 = sBias[128 + chG], bf1 = sBias[129 + chG];
            const float bg0 = sBias[256 + chG], bg1 = sBias[257 + chG];
            const float bo0 = sBias[384 + chG], bo1 = sBias[385 + chG];
            #pragma unroll
            for (int mi = 0; mi < 4; mi++)
                #pragma unroll
                for (int hf = 0; hf < 2; hf++) {
                    const int row = mi * 16 + (lane >> 2) + hf * 8;
                    const int q0 = 2 * hf, ci = mi * 4 + hf * 2;
                    float c0 = sigm(acc[mi][1][q0] + bf0) * cst[ci]
                             + sigm(acc[mi][0][q0] + bi0) * tanh_f(acc[mi][2][q0] + bg0);
                    float c1 = sigm(acc[mi][1][q0+1] + bf1) * cst[ci+1]
                             + sigm(acc[mi][0][q0+1] + bi1) * tanh_f(acc[mi][2][q0+1] + bg1);
                    cst[ci] = c0; cst[ci + 1] = c1;
                    float h0 = sigm(acc[mi][3][q0] + bo0) * tanh_f(c0);
                    float h1 = sigm(acc[mi][3][q0+1] + bo1) * tanh_f(c1);
                    __nv_bfloat16 a0 = __float2bfloat16(h0), a1 = __float2bfloat16(h1);
                    __nv_bfloat162 hp; hp.x = a0; hp.y = a1;
                    __nv_bfloat162 lp;
                    lp.x = __float2bfloat16(h0 - __bfloat162float(a0));
                    lp.y = __float2bfloat16(h1 - __bfloat162float(a1));
                    *(__nv_bfloat162*)(sAh + row * AST + 128 + chG) = hp;
                    *(__nv_bfloat162*)(sAl + row * AST + 128 + chG) = lp;
                    sAf[(128 + chG) * AFS + row] = h0;
                    sAf[(129 + chG) * AFS + row] = h1;
                    float2 hv; hv.x = h0; hv.y = h1;
                    *(float2*)(d_H + ((size_t)t * BB + b0 + row) * CC + chG) = hv;
                }
        } else {
            // ---- FMA engine: channels 64..127, exact fp32 ----
            ull acc[8][4];
            #pragma unroll
            for (int i = 0; i < 8; i++)
                #pragma unroll
                for (int j = 0; j < 4; j++) acc[i][j] = 0ULL;
            const int rbase = eidx * 8;

            for (int c = 0; c < 16; c++) {
                if (c == 8) BAR_ALL();
                WAITG1();
                BAR_F();
                const int ch = ordF[c];
                const float* wbuf = (const float*)(dsm + OFF_RF + (c & 1) * 16384);
                #pragma unroll 2
                for (int kk = 0; kk < 16; kk++) {
                    const int k = ch * 16 + kk;
                    const ull* wr = (const ull*)(wbuf + kk * 256) + lane;
                    ull w0 = wr[0], w1 = wr[32], w2 = wr[64], w3 = wr[96];
                    const float4* ap = (const float4*)(sAf + k * AFS + rbase);
                    float4 a0 = ap[0], a1 = ap[1];
                    ull rp[8];
                    rp[0] = dup2(a0.x); rp[1] = dup2(a0.y);
                    rp[2] = dup2(a0.z); rp[3] = dup2(a0.w);
                    rp[4] = dup2(a1.x); rp[5] = dup2(a1.y);
                    rp[6] = dup2(a1.z); rp[7] = dup2(a1.w);
                    #pragma unroll
                    for (int i = 0; i < 8; i++) {
                        ffma2(acc[i][0], w0, rp[i]);
                        ffma2(acc[i][1], w1, rp[i]);
                        ffma2(acc[i][2], w2, rp[i]);
                        ffma2(acc[i][3], w3, rp[i]);
                    }
                }
                BAR_F();
                const char* src = (const char*)d_WF + ordF[(c + 2) & 15] * 16384 + eTid * 64;
                uint32_t dst = rFU + (c & 1) * 16384 + eTid * 64;
                #pragma unroll
                for (int q = 0; q < 4; q++) CPA16(dst + q * 16, src + q * 16);
                COMMIT();
            }
            // F cell update: ch pair 64+2*lane, rows rbase..+7
            const int chG = 64 + 2 * lane;
            const float bi0 = sBias[chG],       bi1 = sBias[chG + 1];
            const float bf0 = sBias[128 + chG], bf1 = sBias[129 + chG];
            const float bg0 = sBias[256 + chG], bg1 = sBias[257 + chG];
            const float bo0 = sBias[384 + chG], bo1 = sBias[385 + chG];
            #pragma unroll
            for (int i = 0; i < 8; i++) {
                const int row = rbase + i;
                float2 gi = unpk(acc[i][0]), gf = unpk(acc[i][1]);
                float2 gg = unpk(acc[i][2]), go = unpk(acc[i][3]);
                float c0 = sigm(gf.x + bf0) * cst[2*i]   + sigm(gi.x + bi0) * tanh_f(gg.x + bg0);
                float c1 = sigm(gf.y + bf1) * cst[2*i+1] + sigm(gi.y + bi1) * tanh_f(gg.y + bg1);
                cst[2*i] = c0; cst[2*i+1] = c1;
                float h0 = sigm(go.x + bo0) * tanh_f(c0);
                float h1 = sigm(go.y + bo1) * tanh_f(c1);
                __nv_bfloat16 a0 = __float2bfloat16(h0), a1 = __float2bfloat16(h1);
                __nv_bfloat162 hp; hp.x = a0; hp.y = a1;
                __nv_bfloat162 lp;
                lp.x = __float2bfloat16(h0 - __bfloat162float(a0));
                lp.y = __float2bfloat16(h1 - __bfloat162float(a1));
                *(__nv_bfloat162*)(sAh + row * AST + 128 + chG) = hp;
                *(__nv_bfloat162*)(sAl + row * AST + 128 + chG) = lp;
                sAf[(128 + chG) * AFS + row] = h0;
                sAf[(129 + chG) * AFS + row] = h1;
                float2 hv; hv.x = h0; hv.y = h1;
                *(float2*)(d_H + ((size_t)t * BB + b0 + row) * CC + chG) = hv;
            }
        }
        __syncthreads();   // h fully written before next step's readers
    }
}

__global__ void k_out(const float* __restrict__ W_out, const float* __restrict__ b_out) {
    __shared__ float sW[DOUT * CC];
    __shared__ float sb[DOUT];
    int tid = threadIdx.x;
    for (int i = tid; i < DOUT * CC; i += 256) sW[i] = W_out[i];
    if (tid < DOUT) sb[tid] = b_out[tid];
    __syncthreads();
    size_t g = (size_t)blockIdx.x * 256 + tid;
    const float4* h4 = (const float4*)(d_H + g * CC);
    float y0 = sb[0], y1 = sb[1], y2 = sb[2], y3 = sb[3], y4 = sb[4];
    #pragma unroll 8
    for (int c = 0; c < CC / 4; c++) {
        float4 h = h4[c];
        const float4* w4 = (const float4*)sW + c;
        float4 a = w4[0], b = w4[32], d = w4[64], e = w4[96], f = w4[128];
        y0 += h.x * a.x + h.y * a.y + h.z * a.z + h.w * a.w;
        y1 += h.x * b.x + h.y * b.y + h.z * b.z + h.w * b.w;
        y2 += h.x * d.x + h.y * d.y + h.z * d.z + h.w * d.w;
        y3 += h.x * e.x + h.y * e.y + h.z * e.z + h.w * e.w;
        y4 += h.x * f.x + h.y * f.y + h.z * f.z + h.w * f.w;
    }
    float* yo = d_Y + g * DOUT;
    yo[0] = y0; yo[1] = y1; yo[2] = y2; yo[3] = y3; yo[4] = y4;
}

__global__ void k_final(const float* __restrict__ g_out, const float* __restrict__ be_out,
                        float* __restrict__ out) {
    int t = blockIdx.x, tid = threadIdx.x;
    float s1[DOUT], s2[DOUT];
    #pragma unroll
    for (int o = 0; o < DOUT; o++) { s1[o] = 0.f; s2[o] = 0.f; }
    for (int b = tid; b < BB; b += 256) {
        const float* y = d_Y + ((size_t)t * BB + b) * DOUT;
        #pragma unroll
        for (int o = 0; o < DOUT; o++) { float v = y[o]; s1[o] += v; s2[o] += v * v; }
    }
    __shared__ float r1[DOUT][256], r2[DOUT][256];
    #pragma unroll
    for (int o = 0; o < DOUT; o++) { r1[o][tid] = s1[o]; r2[o][tid] = s2[o]; }
    __syncthreads();
    for (int s = 128; s > 0; s >>= 1) {
        if (tid < s)
            #pragma unroll
            for (int o = 0; o < DOUT; o++) {
                r1[o][tid] += r1[o][tid + s]; r2[o][tid] += r2[o][tid + s];
            }
        __syncthreads();
    }
    __shared__ float mu[DOUT], rs[DOUT], bb[DOUT];
    if (tid < DOUT) {
        float m = r1[tid][0] * (1.0f / BB);
        float v = r2[tid][0] * (1.0f / BB) - m * m;
        mu[tid] = m; rs[tid] = rsqrtf(v + EPSV) * g_out[tid]; bb[tid] = be_out[tid];
    }
    __syncthreads();
    for (int b = tid; b < BB; b += 256) {
        const float* y = d_Y + ((size_t)t * BB + b) * DOUT;
        float* op = out + ((size_t)b * TT + t) * DOUT;
        #pragma unroll
        for (int o = 0; o < DOUT; o++)
            op[o] = fmaxf(fmaf(y[o] - mu[o], rs[o], bb[o]), 0.f);
    }
}

extern "C" void kernel_launch(void* const* d_in, const int* in_sizes, int n_in,
                              void* d_out, int out_size) {
    const float* inp    = (const float*)d_in[0];
    const float* W_emb  = (const float*)d_in[1];
    const float* b_emb  = (const float*)d_in[2];
    const float* g_emb  = (const float*)d_in[3];
    const float* be_emb = (const float*)d_in[4];
    const float* W_ih   = (const float*)d_in[5];
    const float* W_hh   = (const float*)d_in[6];
    const float* b_ih   = (const float*)d_in[7];
    const float* b_hh   = (const float*)d_in[8];
    const float* W_out  = (const float*)d_in[9];
    const float* b_out  = (const float*)d_in[10];
    const float* g_out  = (const float*)d_in[11];
    const float* be_out = (const float*)d_in[12];
    float* out = (float*)d_out;

    cudaFuncSetAttribute(k_lstm, cudaFuncAttributeMaxDynamicSharedMemorySize, DSM_REQ);

    k_moments<<<TT, 256>>>(inp);
    k_prep<<<512, 256>>>(W_emb, b_emb, g_emb, be_emb, W_ih, W_hh, b_ih, b_hh);
    k_lstm<<<NCTA, 512, DSM_REQ>>>(inp);
    k_out<<<(TT * BB) / 256, 256>>>(W_out, b_out);
    k_final<<<TT, 256>>>(g_out, be_out, out);
}

// round 13
// speedup vs baseline: 2.3665x; 2.1290x over previous
#include <cuda_runtime.h>
#include <cuda_fp16.h>
#include <cstdint>

#define BB 8192
#define TT 128
#define EE 128
#define CC 128
#define DOUT 5
#define BM 64
#define NCTA 128
#define EPSV 1e-5f
#define AST 264                     // A tile row stride (halfs) = 528B
#define OFF_AL 33792
#define OFF_R  67584                // ring: 2 x 32KB
#define DSM_REQ (OFF_R + 65536 + 1024)
#define SWZ64(x) ((x) ^ (((x) >> 3) & 0x30))

__device__ float d_mom[TT * 5];
__device__ float d_A[TT * EE], d_Bc[TT * EE], d_Cc[TT * EE];
__device__ float d_bias[512];
__device__ __align__(256) __half d_WT[8 * 16384];  // 8 chunks x 32KB: [n512][k32] SW64 fp16
__device__ float d_H[(size_t)TT * BB * CC];
__device__ float d_Y[(size_t)TT * BB * DOUT];

__device__ __forceinline__ float sigm(float x) { return __fdividef(1.f, 1.f + __expf(-x)); }
__device__ __forceinline__ float tanh_f(float x) { return 1.f - __fdividef(2.f, __expf(2.f * x) + 1.f); }
__device__ __forceinline__ uint32_t s2u(const void* p) {
    uint32_t a;
    asm("{ .reg .u64 t; cvta.to.shared.u64 t, %1; cvt.u32.u64 %0, t; }" : "=r"(a) : "l"(p));
    return a;
}
#define CPA16(dst, src) \
    asm volatile("cp.async.cg.shared.global [%0], [%1], 16;" :: "r"(dst), "l"(src))
#define LDSM4(r, a) \
    asm volatile("ldmatrix.sync.aligned.m8n8.x4.shared.b16 {%0,%1,%2,%3}, [%4];" \
        : "=r"((r)[0]), "=r"((r)[1]), "=r"((r)[2]), "=r"((r)[3]) : "r"(a))
#define MMAF16(d, a, b0, b1) \
    asm volatile("mma.sync.aligned.m16n8k16.row.col.f32.f16.f16.f32 " \
        "{%0,%1,%2,%3}, {%4,%5,%6,%7}, {%8,%9}, {%0,%1,%2,%3};" \
        : "+f"((d)[0]), "+f"((d)[1]), "+f"((d)[2]), "+f"((d)[3]) \
        : "r"((a)[0]), "r"((a)[1]), "r"((a)[2]), "r"((a)[3]), "r"(b0), "r"(b1))
#define WAITG1() asm volatile("cp.async.wait_group 1;" ::: "memory")
#define COMMIT() asm volatile("cp.async.commit_group;")

__global__ void k_moments(const float* __restrict__ inp) {
    int t = blockIdx.x, tid = threadIdx.x;
    float su = 0, sv = 0, suu = 0, svv = 0, suv = 0;
    for (int b = tid; b < BB; b += 256) {
        float2 uv = *(const float2*)(inp + ((size_t)b * TT + t) * 2);
        su += uv.x; sv += uv.y; suu += uv.x * uv.x; svv += uv.y * uv.y; suv += uv.x * uv.y;
    }
    __shared__ float red[5][256];
    red[0][tid] = su; red[1][tid] = sv; red[2][tid] = suu; red[3][tid] = svv; red[4][tid] = suv;
    __syncthreads();
    for (int s = 128; s > 0; s >>= 1) {
        if (tid < s)
            for (int m = 0; m < 5; m++) red[m][tid] += red[m][tid + s];
        __syncthreads();
    }
    if (tid < 5) d_mom[t * 5 + tid] = red[tid][0] * (1.0f / BB);
}

// Weight chunk c (0..7): k rows c*32..+31. Storage n = w*32 + g*8 + chL
// -> orig row g*128 + (w*8 + chL). fp16, SW64-swizzled 64B rows.
__global__ void k_prep(const float* __restrict__ W_emb, const float* __restrict__ b_emb,
                       const float* __restrict__ g_emb, const float* __restrict__ be_emb,
                       const float* __restrict__ W_ih, const float* __restrict__ W_hh,
                       const float* __restrict__ b_ih, const float* __restrict__ b_hh) {
    int idx = blockIdx.x * 256 + threadIdx.x;   // 512 blocks -> 131072
    if (idx < 131072) {
        int c = idx >> 14, rem = idx & 16383;
        int n = rem >> 5, kl = rem & 31;
        int w = n >> 5, q = n & 31, g = q >> 3, chL = q & 7;
        int row = g * 128 + w * 8 + chL;
        int k_orig = c * 32 + kl;
        float wv = (k_orig < 128) ? W_ih[row * 128 + k_orig]
                                  : W_hh[row * 128 + (k_orig - 128)];
        *(__half*)((char*)d_WT + c * 32768 + SWZ64((uint32_t)(n * 64 + kl * 2))) =
            __float2half_rn(wv);
    }
    if (idx < 512) d_bias[idx] = b_ih[idx] + b_hh[idx];
    if (idx < TT * EE) {
        int t = idx >> 7, e = idx & 127;
        float w0 = W_emb[e * 2], w1 = W_emb[e * 2 + 1], bb = b_emb[e];
        float mu_u = d_mom[t * 5], mu_v = d_mom[t * 5 + 1];
        float vu = d_mom[t * 5 + 2] - mu_u * mu_u;
        float vv = d_mom[t * 5 + 3] - mu_v * mu_v;
        float cuv = d_mom[t * 5 + 4] - mu_u * mu_v;
        float mu = w0 * mu_u + w1 * mu_v + bb;
        float var = w0 * w0 * vu + w1 * w1 * vv + 2.f * w0 * w1 * cuv;
        float sc = g_emb[e] * rsqrtf(var + EPSV);
        d_A[idx] = sc * w0; d_Bc[idx] = sc * w1;
        d_Cc[idx] = sc * (bb - mu) + be_emb[e];
    }
}

__global__ void __launch_bounds__(512, 1)
k_lstm(const float* __restrict__ inp) {
    extern __shared__ char dsm_raw[];
    const uint32_t rawU = s2u(dsm_raw);
    const uint32_t base = (rawU + 1023) & ~1023u;
    char* dsm = dsm_raw + (base - rawU);
    __half* sAh = (__half*)dsm;
    __half* sAl = (__half*)(dsm + OFF_AL);
    const uint32_t AhU = base, AlU = base + OFF_AL, ringU = base + OFF_R;

    __shared__ float sBias[512];
    __shared__ float sAe[EE], sBe[EE], sCe[EE];
    __shared__ float sUV[BM * 2];

    const int tid = threadIdx.x, lane = tid & 31, wid = tid >> 5;
    const int b0 = blockIdx.x * BM;
    const int grp = lane >> 3, li = lane & 7;
    const int rowA = (grp & 1) * 8 + li;
    const int kaddA = (grp >> 1) * 8;

    if (tid < 512) sBias[tid] = d_bias[tid];
    for (int i = tid; i < 4096; i += 512) {          // zero h region (cols 128..255)
        int r = i >> 6, q = i & 63;
        *(uint32_t*)(sAh + r * AST + 128 + 2 * q) = 0;
        *(uint32_t*)(sAl + r * AST + 128 + 2 * q) = 0;
    }
    __syncthreads();

    // prologue (once): chunks 0,1 into ring slots 0,1
    #pragma unroll
    for (int pc = 0; pc < 2; pc++) {
        const char* src = (const char*)d_WT + pc * 32768 + tid * 64;
        uint32_t dst = ringU + pc * 32768 + tid * 64;
        #pragma unroll
        for (int q = 0; q < 4; q++) CPA16(dst + q * 16, src + q * 16);
        COMMIT();
    }

    float cst[16];
    #pragma unroll
    for (int i = 0; i < 16; i++) cst[i] = 0.f;

    for (int t = 0; t < TT; t++) {
        if (tid < BM) {
            float2 uv = *(const float2*)(inp + ((size_t)(b0 + tid) * TT + t) * 2);
            sUV[tid * 2] = uv.x; sUV[tid * 2 + 1] = uv.y;
        }
        if (tid < EE) {
            sAe[tid] = d_A[t * EE + tid];
            sBe[tid] = d_Bc[t * EE + tid];
            sCe[tid] = d_Cc[t * EE + tid];
        }
        __syncthreads();

        // xbn -> A cols 0..127 (fp16 hi/lo)
        for (int i = tid; i < 4096; i += 512) {
            int r = i >> 6, ep = i & 63, e = 2 * ep;
            float u = sUV[2 * r], v = sUV[2 * r + 1];
            float x0 = fmaxf(fmaf(sAe[e], u, fmaf(sBe[e], v, sCe[e])), 0.f);
            float x1 = fmaxf(fmaf(sAe[e + 1], u, fmaf(sBe[e + 1], v, sCe[e + 1])), 0.f);
            __half h0 = __float2half_rn(x0), h1 = __float2half_rn(x1);
            __half2 hp; hp.x = h0; hp.y = h1;
            __half2 lp;
            lp.x = __float2half_rn(x0 - __half2float(h0));
            lp.y = __float2half_rn(x1 - __half2float(h1));
            *(__half2*)(sAh + r * AST + e) = hp;
            *(__half2*)(sAl + r * AST + e) = lp;
        }

        float acc[4][4][4];
        #pragma unroll
        for (int a = 0; a < 4; a++)
            #pragma unroll
            for (int g = 0; g < 4; g++)
                #pragma unroll
                for (int q = 0; q < 4; q++) acc[a][g][q] = 0.f;

        // 8 k-chunks x 2 A-passes (hi, lo)
        for (int c = 0; c < 8; c++) {
            WAITG1();
            __syncthreads();
            const uint32_t slotU = ringU + (c & 1) * 32768;
            uint32_t bfr[4][4];
            #pragma unroll
            for (int g = 0; g < 4; g++) {
                uint32_t nrow = (uint32_t)(wid * 32 + g * 8 + li);
                LDSM4(bfr[g], slotU + SWZ64(nrow * 64 + (uint32_t)grp * 16));
            }
            const int kb = c * 32;
            #pragma unroll
            for (int rep = 0; rep < 2; rep++) {
                const uint32_t aU = rep ? AlU : AhU;
                #pragma unroll
                for (int ks = 0; ks < 2; ks++)
                    #pragma unroll
                    for (int mi = 0; mi < 4; mi++) {
                        uint32_t af[4];
                        LDSM4(af, aU + (uint32_t)((mi * 16 + rowA) * AST +
                                                  kb + ks * 16 + kaddA) * 2);
                        #pragma unroll
                        for (int g = 0; g < 4; g++)
                            MMAF16(acc[mi][g], af, bfr[g][2 * ks], bfr[g][2 * ks + 1]);
                    }
            }
            __syncthreads();
            {   // refill slot with chunk (c+2)&7 — ring wraps across steps
                const char* src = (const char*)d_WT + ((c + 2) & 7) * 32768 + tid * 64;
                uint32_t dst = ringU + (c & 1) * 32768 + tid * 64;
                #pragma unroll
                for (int q = 0; q < 4; q++) CPA16(dst + q * 16, src + q * 16);
                COMMIT();
            }
        }

        // cell update: thread owns channels {ch0, ch0+1}, rows mi*16+(lane>>2)+8*hf
        const int ch0 = wid * 8 + 2 * (lane & 3);
        const float bi0 = sBias[ch0],       bi1 = sBias[ch0 + 1];
        const float bf0 = sBias[128 + ch0], bf1 = sBias[129 + ch0];
        const float bg0 = sBias[256 + ch0], bg1 = sBias[257 + ch0];
        const float bo0 = sBias[384 + ch0], bo1 = sBias[385 + ch0];
        #pragma unroll
        for (int mi = 0; mi < 4; mi++)
            #pragma unroll
            for (int hf = 0; hf < 2; hf++) {
                const int row = mi * 16 + (lane >> 2) + 8 * hf;
                const int q0 = 2 * hf, ci = mi * 4 + 2 * hf;
                float c0 = sigm(acc[mi][1][q0] + bf0) * cst[ci]
                         + sigm(acc[mi][0][q0] + bi0) * tanh_f(acc[mi][2][q0] + bg0);
                float c1 = sigm(acc[mi][1][q0 + 1] + bf1) * cst[ci + 1]
                         + sigm(acc[mi][0][q0 + 1] + bi1) * tanh_f(acc[mi][2][q0 + 1] + bg1);
                cst[ci] = c0; cst[ci + 1] = c1;
                float h0 = sigm(acc[mi][3][q0] + bo0) * tanh_f(c0);
                float h1 = sigm(acc[mi][3][q0 + 1] + bo1) * tanh_f(c1);
                __half a0 = __float2half_rn(h0), a1 = __float2half_rn(h1);
                __half2 hp; hp.x = a0; hp.y = a1;
                __half2 lp;
                lp.x = __float2half_rn(h0 - __half2float(a0));
                lp.y = __float2half_rn(h1 - __half2float(a1));
                *(__half2*)(sAh + row * AST + 128 + ch0) = hp;
                *(__half2*)(sAl + row * AST + 128 + ch0) = lp;
                float2 hv; hv.x = h0; hv.y = h1;
                *(float2*)(d_H + ((size_t)t * BB + b0 + row) * CC + ch0) = hv;
            }
        __syncthreads();
    }
}

__global__ void k_out(const float* __restrict__ W_out, const float* __restrict__ b_out) {
    __shared__ float sW[DOUT * CC];
    __shared__ float sb[DOUT];
    int tid = threadIdx.x;
    for (int i = tid; i < DOUT * CC; i += 256) sW[i] = W_out[i];
    if (tid < DOUT) sb[tid] = b_out[tid];
    __syncthreads();
    size_t g = (size_t)blockIdx.x * 256 + tid;
    const float4* h4 = (const float4*)(d_H + g * CC);
    float y0 = sb[0], y1 = sb[1], y2 = sb[2], y3 = sb[3], y4 = sb[4];
    #pragma unroll 8
    for (int c = 0; c < CC / 4; c++) {
        float4 h = h4[c];
        const float4* w4 = (const float4*)sW + c;
        float4 a = w4[0], b = w4[32], d = w4[64], e = w4[96], f = w4[128];
        y0 += h.x * a.x + h.y * a.y + h.z * a.z + h.w * a.w;
        y1 += h.x * b.x + h.y * b.y + h.z * b.z + h.w * b.w;
        y2 += h.x * d.x + h.y * d.y + h.z * d.z + h.w * d.w;
        y3 += h.x * e.x + h.y * e.y + h.z * e.z + h.w * e.w;
        y4 += h.x * f.x + h.y * f.y + h.z * f.z + h.w * f.w;
    }
    float* yo = d_Y + g * DOUT;
    yo[0] = y0; yo[1] = y1; yo[2] = y2; yo[3] = y3; yo[4] = y4;
}

__global__ void k_final(const float* __restrict__ g_out, const float* __restrict__ be_out,
                        float* __restrict__ out) {
    int t = blockIdx.x, tid = threadIdx.x;
    float s1[DOUT], s2[DOUT];
    #pragma unroll
    for (int o = 0; o < DOUT; o++) { s1[o] = 0.f; s2[o] = 0.f; }
    for (int b = tid; b < BB; b += 256) {
        const float* y = d_Y + ((size_t)t * BB + b) * DOUT;
        #pragma unroll
        for (int o = 0; o < DOUT; o++) { float v = y[o]; s1[o] += v; s2[o] += v * v; }
    }
    __shared__ float r1[DOUT][256], r2[DOUT][256];
    #pragma unroll
    for (int o = 0; o < DOUT; o++) { r1[o][tid] = s1[o]; r2[o][tid] = s2[o]; }
    __syncthreads();
    for (int s = 128; s > 0; s >>= 1) {
        if (tid < s)
            #pragma unroll
            for (int o = 0; o < DOUT; o++) {
                r1[o][tid] += r1[o][tid + s]; r2[o][tid] += r2[o][tid + s];
            }
        __syncthreads();
    }
    __shared__ float mu[DOUT], rs[DOUT], bb[DOUT];
    if (tid < DOUT) {
        float m = r1[tid][0] * (1.0f / BB);
        float v = r2[tid][0] * (1.0f / BB) - m * m;
        mu[tid] = m; rs[tid] = rsqrtf(v + EPSV) * g_out[tid]; bb[tid] = be_out[tid];
    }
    __syncthreads();
    for (int b = tid; b < BB; b += 256) {
        const float* y = d_Y + ((size_t)t * BB + b) * DOUT;
        float* op = out + ((size_t)b * TT + t) * DOUT;
        #pragma unroll
        for (int o = 0; o < DOUT; o++)
            op[o] = fmaxf(fmaf(y[o] - mu[o], rs[o], bb[o]), 0.f);
    }
}

extern "C" void kernel_launch(void* const* d_in, const int* in_sizes, int n_in,
                              void* d_out, int out_size) {
    const float* inp    = (const float*)d_in[0];
    const float* W_emb  = (const float*)d_in[1];
    const float* b_emb  = (const float*)d_in[2];
    const float* g_emb  = (const float*)d_in[3];
    const float* be_emb = (const float*)d_in[4];
    const float* W_ih   = (const float*)d_in[5];
    const float* W_hh   = (const float*)d_in[6];
    const float* b_ih   = (const float*)d_in[7];
    const float* b_hh   = (const float*)d_in[8];
    const float* W_out  = (const float*)d_in[9];
    const float* b_out  = (const float*)d_in[10];
    const float* g_out  = (const float*)d_in[11];
    const float* be_out = (const float*)d_in[12];
    float* out = (float*)d_out;

    cudaFuncSetAttribute(k_lstm, cudaFuncAttributeMaxDynamicSharedMemorySize, DSM_REQ);

    k_moments<<<TT, 256>>>(inp);
    k_prep<<<512, 256>>>(W_emb, b_emb, g_emb, be_emb, W_ih, W_hh, b_ih, b_hh);
    k_lstm<<<NCTA, 512, DSM_REQ>>>(inp);
    k_out<<<(TT * BB) / 256, 256>>>(W_out, b_out);
    k_final<<<TT, 256>>>(g_out, be_out, out);
}

// round 15
// speedup vs baseline: 3.3709x; 1.4244x over previous
#include <cuda_runtime.h>
#include <cuda_fp16.h>
#include <cstdint>

#define BB 8192
#define TT 128
#define EE 128
#define CC 128
#define DOUT 5
#define BM 64
#define NCTA 128
#define EPSV 1e-5f
#define AST 264                     // A tile row stride (halfs) = 528B
#define OFF_R  33792                // ring: 2 x 32KB after sAh
#define DSM_REQ (OFF_R + 65536 + 1024)
#define SWZ64(x) ((x) ^ (((x) >> 3) & 0x30))

__device__ float d_mom[TT * 5];
__device__ float d_A[TT * EE], d_Bc[TT * EE], d_Cc[TT * EE];
__device__ float d_bias[512];
__device__ __align__(256) __half d_WT[8 * 16384];  // 8 chunks x 32KB: [n512][k32] SW64 fp16
__device__ float d_Y[(size_t)TT * BB * DOUT];

__device__ __forceinline__ float sigm(float x) { return __fdividef(1.f, 1.f + __expf(-x)); }
__device__ __forceinline__ float tanh_f(float x) { return 1.f - __fdividef(2.f, __expf(2.f * x) + 1.f); }
__device__ __forceinline__ uint32_t s2u(const void* p) {
    uint32_t a;
    asm("{ .reg .u64 t; cvta.to.shared.u64 t, %1; cvt.u32.u64 %0, t; }" : "=r"(a) : "l"(p));
    return a;
}
#define CPA16(dst, src) \
    asm volatile("cp.async.cg.shared.global [%0], [%1], 16;" :: "r"(dst), "l"(src))
#define LDSM4(r, a) \
    asm volatile("ldmatrix.sync.aligned.m8n8.x4.shared.b16 {%0,%1,%2,%3}, [%4];" \
        : "=r"((r)[0]), "=r"((r)[1]), "=r"((r)[2]), "=r"((r)[3]) : "r"(a))
#define MMAF16(d, a, b0, b1) \
    asm volatile("mma.sync.aligned.m16n8k16.row.col.f32.f16.f16.f32 " \
        "{%0,%1,%2,%3}, {%4,%5,%6,%7}, {%8,%9}, {%0,%1,%2,%3};" \
        : "+f"((d)[0]), "+f"((d)[1]), "+f"((d)[2]), "+f"((d)[3]) \
        : "r"((a)[0]), "r"((a)[1]), "r"((a)[2]), "r"((a)[3]), "r"(b0), "r"(b1))
#define WAITG1() asm volatile("cp.async.wait_group 1;" ::: "memory")
#define COMMIT() asm volatile("cp.async.commit_group;")

__global__ void k_moments(const float* __restrict__ inp) {
    int t = blockIdx.x, tid = threadIdx.x;
    float su = 0, sv = 0, suu = 0, svv = 0, suv = 0;
    for (int b = tid; b < BB; b += 256) {
        float2 uv = *(const float2*)(inp + ((size_t)b * TT + t) * 2);
        su += uv.x; sv += uv.y; suu += uv.x * uv.x; svv += uv.y * uv.y; suv += uv.x * uv.y;
    }
    __shared__ float red[5][256];
    red[0][tid] = su; red[1][tid] = sv; red[2][tid] = suu; red[3][tid] = svv; red[4][tid] = suv;
    __syncthreads();
    for (int s = 128; s > 0; s >>= 1) {
        if (tid < s)
            for (int m = 0; m < 5; m++) red[m][tid] += red[m][tid + s];
        __syncthreads();
    }
    if (tid < 5) d_mom[t * 5 + tid] = red[tid][0] * (1.0f / BB);
}

// Weight chunk c (0..7): k rows c*32..+31. Storage n = w*32 + g*8 + chL
// -> orig row g*128 + (w*8 + chL). fp16, SW64-swizzled 64B rows.
__global__ void k_prep(const float* __restrict__ W_emb, const float* __restrict__ b_emb,
                       const float* __restrict__ g_emb, const float* __restrict__ be_emb,
                       const float* __restrict__ W_ih, const float* __restrict__ W_hh,
                       const float* __restrict__ b_ih, const float* __restrict__ b_hh) {
    int idx = blockIdx.x * 256 + threadIdx.x;   // 512 blocks -> 131072
    if (idx < 131072) {
        int c = idx >> 14, rem = idx & 16383;
        int n = rem >> 5, kl = rem & 31;
        int w = n >> 5, q = n & 31, g = q >> 3, chL = q & 7;
        int row = g * 128 + w * 8 + chL;
        int k_orig = c * 32 + kl;
        float wv = (k_orig < 128) ? W_ih[row * 128 + k_orig]
                                  : W_hh[row * 128 + (k_orig - 128)];
        *(__half*)((char*)d_WT + c * 32768 + SWZ64((uint32_t)(n * 64 + kl * 2))) =
            __float2half_rn(wv);
    }
    if (idx < 512) d_bias[idx] = b_ih[idx] + b_hh[idx];
    if (idx < TT * EE) {
        int t = idx >> 7, e = idx & 127;
        float w0 = W_emb[e * 2], w1 = W_emb[e * 2 + 1], bb = b_emb[e];
        float mu_u = d_mom[t * 5], mu_v = d_mom[t * 5 + 1];
        float vu = d_mom[t * 5 + 2] - mu_u * mu_u;
        float vv = d_mom[t * 5 + 3] - mu_v * mu_v;
        float cuv = d_mom[t * 5 + 4] - mu_u * mu_v;
        float mu = w0 * mu_u + w1 * mu_v + bb;
        float var = w0 * w0 * vu + w1 * w1 * vv + 2.f * w0 * w1 * cuv;
        float sc = g_emb[e] * rsqrtf(var + EPSV);
        d_A[idx] = sc * w0; d_Bc[idx] = sc * w1;
        d_Cc[idx] = sc * (bb - mu) + be_emb[e];
    }
}

__global__ void __launch_bounds__(512, 1)
k_lstm(const float* __restrict__ inp, const float* __restrict__ W_out) {
    extern __shared__ char dsm_raw[];
    const uint32_t rawU = s2u(dsm_raw);
    const uint32_t base = (rawU + 1023) & ~1023u;
    char* dsm = dsm_raw + (base - rawU);
    __half* sAh = (__half*)dsm;
    const uint32_t AhU = base, ringU = base + OFF_R;

    __shared__ float sBias[512];
    __shared__ float sAe[EE], sBe[EE], sCe[EE];
    __shared__ float sUV[BM * 2];
    __shared__ float sH[BM * 130];        // fp32 h for output head
    __shared__ float sWo[DOUT * CC];

    const int tid = threadIdx.x, lane = tid & 31, wid = tid >> 5;
    const int b0 = blockIdx.x * BM;
    const int grp = lane >> 3, li = lane & 7;
    const int rowA = (grp & 1) * 8 + li;
    const int kaddA = (grp >> 1) * 8;

    if (tid < 512) sBias[tid] = d_bias[tid];
    for (int i = tid; i < DOUT * CC; i += 512) sWo[i] = W_out[i];
    for (int i = tid; i < 4096; i += 512) {          // zero h region (cols 128..255)
        int r = i >> 6, q = i & 63;
        *(uint32_t*)(sAh + r * AST + 128 + 2 * q) = 0;
    }
    __syncthreads();

    // prologue (once): chunks 0,1 into ring slots 0,1
    #pragma unroll
    for (int pc = 0; pc < 2; pc++) {
        const char* src = (const char*)d_WT + pc * 32768 + tid * 64;
        uint32_t dst = ringU + pc * 32768 + tid * 64;
        #pragma unroll
        for (int q = 0; q < 4; q++) CPA16(dst + q * 16, src + q * 16);
        COMMIT();
    }

    float cst[16];
    #pragma unroll
    for (int i = 0; i < 16; i++) cst[i] = 0.f;

    for (int t = 0; t < TT; t++) {
        if (tid < BM) {
            float2 uv = *(const float2*)(inp + ((size_t)(b0 + tid) * TT + t) * 2);
            sUV[tid * 2] = uv.x; sUV[tid * 2 + 1] = uv.y;
        }
        if (tid < EE) {
            sAe[tid] = d_A[t * EE + tid];
            sBe[tid] = d_Bc[t * EE + tid];
            sCe[tid] = d_Cc[t * EE + tid];
        }
        __syncthreads();

        // xbn -> A cols 0..127 (single fp16)
        for (int i = tid; i < 4096; i += 512) {
            int r = i >> 6, ep = i & 63, e = 2 * ep;
            float u = sUV[2 * r], v = sUV[2 * r + 1];
            float x0 = fmaxf(fmaf(sAe[e], u, fmaf(sBe[e], v, sCe[e])), 0.f);
            float x1 = fmaxf(fmaf(sAe[e + 1], u, fmaf(sBe[e + 1], v, sCe[e + 1])), 0.f);
            __half2 hp; hp.x = __float2half_rn(x0); hp.y = __float2half_rn(x1);
            *(__half2*)(sAh + r * AST + e) = hp;
        }

        float acc[4][4][4];
        #pragma unroll
        for (int a = 0; a < 4; a++)
            #pragma unroll
            for (int g = 0; g < 4; g++)
                #pragma unroll
                for (int q = 0; q < 4; q++) acc[a][g][q] = 0.f;

        // 8 k-chunks, single A pass
        for (int c = 0; c < 8; c++) {
            WAITG1();
            __syncthreads();
            const uint32_t slotU = ringU + (c & 1) * 32768;
            uint32_t bfr[4][4];
            #pragma unroll
            for (int g = 0; g < 4; g++) {
                uint32_t nrow = (uint32_t)(wid * 32 + g * 8 + li);
                LDSM4(bfr[g], slotU + SWZ64(nrow * 64 + (uint32_t)grp * 16));
            }
            const int kb = c * 32;
            #pragma unroll
            for (int ks = 0; ks < 2; ks++)
                #pragma unroll
                for (int mi = 0; mi < 4; mi++) {
                    uint32_t af[4];
                    LDSM4(af, AhU + (uint32_t)((mi * 16 + rowA) * AST +
                                               kb + ks * 16 + kaddA) * 2);
                    #pragma unroll
                    for (int g = 0; g < 4; g++)
                        MMAF16(acc[mi][g], af, bfr[g][2 * ks], bfr[g][2 * ks + 1]);
                }
            __syncthreads();
            {   // refill slot with chunk (c+2)&7 — ring wraps across steps
                const char* src = (const char*)d_WT + ((c + 2) & 7) * 32768 + tid * 64;
                uint32_t dst = ringU + (c & 1) * 32768 + tid * 64;
                #pragma unroll
                for (int q = 0; q < 4; q++) CPA16(dst + q * 16, src + q * 16);
                COMMIT();
            }
        }

        // cell update: thread owns channels {ch0, ch0+1}, rows mi*16+(lane>>2)+8*hf
        const int ch0 = wid * 8 + 2 * (lane & 3);
        const float bi0 = sBias[ch0],       bi1 = sBias[ch0 + 1];
        const float bf0 = sBias[128 + ch0], bf1 = sBias[129 + ch0];
        const float bg0 = sBias[256 + ch0], bg1 = sBias[257 + ch0];
        const float bo0 = sBias[384 + ch0], bo1 = sBias[385 + ch0];
        #pragma unroll
        for (int mi = 0; mi < 4; mi++)
            #pragma unroll
            for (int hf = 0; hf < 2; hf++) {
                const int row = mi * 16 + (lane >> 2) + 8 * hf;
                const int q0 = 2 * hf, ci = mi * 4 + 2 * hf;
                float c0 = sigm(acc[mi][1][q0] + bf0) * cst[ci]
                         + sigm(acc[mi][0][q0] + bi0) * tanh_f(acc[mi][2][q0] + bg0);
                float c1 = sigm(acc[mi][1][q0 + 1] + bf1) * cst[ci + 1]
                         + sigm(acc[mi][0][q0 + 1] + bi1) * tanh_f(acc[mi][2][q0 + 1] + bg1);
                cst[ci] = c0; cst[ci + 1] = c1;
                float h0 = sigm(acc[mi][3][q0] + bo0) * tanh_f(c0);
                float h1 = sigm(acc[mi][3][q0 + 1] + bo1) * tanh_f(c1);
                __half2 hp; hp.x = __float2half_rn(h0); hp.y = __float2half_rn(h1);
                *(__half2*)(sAh + row * AST + 128 + ch0) = hp;
                float2 hv; hv.x = h0; hv.y = h1;
                *(float2*)(sH + row * 130 + ch0) = hv;
            }
        __syncthreads();

        // fused output head: y[row][o] = sum_c h[row][c] * Wout[o][c]
        if (tid < 320) {
            const int o = tid >> 6, row = tid & 63;
            const float* hr = sH + row * 130;
            const float* wr = sWo + o * CC;
            float y0 = 0.f, y1 = 0.f, y2 = 0.f, y3 = 0.f;
            #pragma unroll 8
            for (int c2 = 0; c2 < CC; c2 += 4) {
                y0 = fmaf(hr[c2],     wr[c2],     y0);
                y1 = fmaf(hr[c2 + 1], wr[c2 + 1], y1);
                y2 = fmaf(hr[c2 + 2], wr[c2 + 2], y2);
                y3 = fmaf(hr[c2 + 3], wr[c2 + 3], y3);
            }
            d_Y[((size_t)t * BB + b0 + row) * DOUT + o] = (y0 + y1) + (y2 + y3);
        }
        __syncthreads();
    }
}

__global__ void k_final(const float* __restrict__ g_out, const float* __restrict__ be_out,
                        float* __restrict__ out) {
    int t = blockIdx.x, tid = threadIdx.x;
    float s1[DOUT], s2[DOUT];
    #pragma unroll
    for (int o = 0; o < DOUT; o++) { s1[o] = 0.f; s2[o] = 0.f; }
    for (int b = tid; b < BB; b += 256) {
        const float* y = d_Y + ((size_t)t * BB + b) * DOUT;
        #pragma unroll
        for (int o = 0; o < DOUT; o++) { float v = y[o]; s1[o] += v; s2[o] += v * v; }
    }
    __shared__ float r1[DOUT][256], r2[DOUT][256];
    #pragma unroll
    for (int o = 0; o < DOUT; o++) { r1[o][tid] = s1[o]; r2[o][tid] = s2[o]; }
    __syncthreads();
    for (int s = 128; s > 0; s >>= 1) {
        if (tid < s)
            #pragma unroll
            for (int o = 0; o < DOUT; o++) {
                r1[o][tid] += r1[o][tid + s]; r2[o][tid] += r2[o][tid + s];
            }
        __syncthreads();
    }
    __shared__ float mu[DOUT], rs[DOUT], bb[DOUT];
    if (tid < DOUT) {
        float m = r1[tid][0] * (1.0f / BB);
        float v = r2[tid][0] * (1.0f / BB) - m * m;
        mu[tid] = m; rs[tid] = rsqrtf(v + EPSV) * g_out[tid]; bb[tid] = be_out[tid];
    }
    __syncthreads();
    for (int b = tid; b < BB; b += 256) {
        const float* y = d_Y + ((size_t)t * BB + b) * DOUT;
        float* op = out + ((size_t)b * TT + t) * DOUT;
        #pragma unroll
        for (int o = 0; o < DOUT; o++)
            op[o] = fmaxf(fmaf(y[o] - mu[o], rs[o], bb[o]), 0.f);
    }
}

extern "C" void kernel_launch(void* const* d_in, const int* in_sizes, int n_in,
                              void* d_out, int out_size) {
    const float* inp    = (const float*)d_in[0];
    const float* W_emb  = (const float*)d_in[1];
    const float* b_emb  = (const float*)d_in[2];
    const float* g_emb  = (const float*)d_in[3];
    const float* be_emb = (const float*)d_in[4];
    const float* W_ih   = (const float*)d_in[5];
    const float* W_hh   = (const float*)d_in[6];
    const float* b_ih   = (const float*)d_in[7];
    const float* b_hh   = (const float*)d_in[8];
    const float* W_out  = (const float*)d_in[9];
    const float* g_out  = (const float*)d_in[11];
    const float* be_out = (const float*)d_in[12];
    float* out = (float*)d_out;
    // b_out (d_in[10]) provably cancels in batch-BN; unused.

    cudaFuncSetAttribute(k_lstm, cudaFuncAttributeMaxDynamicSharedMemorySize, DSM_REQ);

    k_moments<<<TT, 256>>>(inp);
    k_prep<<<512, 256>>>(W_emb, b_emb, g_emb, be_emb, W_ih, W_hh, b_ih, b_hh);
    k_lstm<<<NCTA, 512, DSM_REQ>>>(inp, W_out);
    k_final<<<TT, 256>>>(g_out, be_out, out);
}

// round 17
// speedup vs baseline: 3.8540x; 1.1433x over previous
#include <cuda_runtime.h>
#include <cuda_fp16.h>
#include <cstdint>

#define BB 8192
#define TT 128
#define EE 128
#define CC 128
#define DOUT 5
#define BM 64
#define NCTA 128
#define EPSV 1e-5f
#define AST 264                     // A tile row stride (halfs) = 528B
#define OFF_R  33792                // ring: 4 x 32KB after sAh
#define DSM_REQ (OFF_R + 4 * 32768 + 1024)
#define SWZ64(x) ((x) ^ (((x) >> 3) & 0x30))

__device__ float d_mom[TT * 5];
__device__ float d_A[TT * EE], d_Bc[TT * EE], d_Cc[TT * EE];
__device__ float d_bias[512];
__device__ __align__(256) __half d_WT[8 * 16384];  // 8 chunks x 32KB: [n512][k32] SW64 fp16
__device__ float d_Y[(size_t)TT * BB * DOUT];

__device__ __forceinline__ float tanh_a(float x) {
    float r; asm("tanh.approx.f32 %0, %1;" : "=f"(r) : "f"(x)); return r;
}
__device__ __forceinline__ float sigm(float x) {
    return fmaf(tanh_a(0.5f * x), 0.5f, 0.5f);
}
__device__ __forceinline__ uint32_t s2u(const void* p) {
    uint32_t a;
    asm("{ .reg .u64 t; cvta.to.shared.u64 t, %1; cvt.u32.u64 %0, t; }" : "=r"(a) : "l"(p));
    return a;
}
#define CPA16(dst, src) \
    asm volatile("cp.async.cg.shared.global [%0], [%1], 16;" :: "r"(dst), "l"(src))
#define LDSM4(r, a) \
    asm volatile("ldmatrix.sync.aligned.m8n8.x4.shared.b16 {%0,%1,%2,%3}, [%4];" \
        : "=r"((r)[0]), "=r"((r)[1]), "=r"((r)[2]), "=r"((r)[3]) : "r"(a))
#define MMAF16(d, a, b0, b1) \
    asm volatile("mma.sync.aligned.m16n8k16.row.col.f32.f16.f16.f32 " \
        "{%0,%1,%2,%3}, {%4,%5,%6,%7}, {%8,%9}, {%0,%1,%2,%3};" \
        : "+f"((d)[0]), "+f"((d)[1]), "+f"((d)[2]), "+f"((d)[3]) \
        : "r"((a)[0]), "r"((a)[1]), "r"((a)[2]), "r"((a)[3]), "r"(b0), "r"(b1))
#define WAITG1() asm volatile("cp.async.wait_group 1;" ::: "memory")
#define COMMIT() asm volatile("cp.async.commit_group;")

__global__ void k_moments(const float* __restrict__ inp) {
    int t = blockIdx.x, tid = threadIdx.x;
    float su = 0, sv = 0, suu = 0, svv = 0, suv = 0;
    for (int b = tid; b < BB; b += 256) {
        float2 uv = *(const float2*)(inp + ((size_t)b * TT + t) * 2);
        su += uv.x; sv += uv.y; suu += uv.x * uv.x; svv += uv.y * uv.y; suv += uv.x * uv.y;
    }
    __shared__ float red[5][256];
    red[0][tid] = su; red[1][tid] = sv; red[2][tid] = suu; red[3][tid] = svv; red[4][tid] = suv;
    __syncthreads();
    for (int s = 128; s > 0; s >>= 1) {
        if (tid < s)
            for (int m = 0; m < 5; m++) red[m][tid] += red[m][tid + s];
        __syncthreads();
    }
    if (tid < 5) d_mom[t * 5 + tid] = red[tid][0] * (1.0f / BB);
}

// Weight chunk c (0..7): k rows c*32..+31. Storage n = w*32 + g*8 + chL
// -> orig row g*128 + (w*8 + chL). fp16, SW64-swizzled 64B rows.
__global__ void k_prep(const float* __restrict__ W_emb, const float* __restrict__ b_emb,
                       const float* __restrict__ g_emb, const float* __restrict__ be_emb,
                       const float* __restrict__ W_ih, const float* __restrict__ W_hh,
                       const float* __restrict__ b_ih, const float* __restrict__ b_hh) {
    int idx = blockIdx.x * 256 + threadIdx.x;   // 512 blocks -> 131072
    if (idx < 131072) {
        int c = idx >> 14, rem = idx & 16383;
        int n = rem >> 5, kl = rem & 31;
        int w = n >> 5, q = n & 31, g = q >> 3, chL = q & 7;
        int row = g * 128 + w * 8 + chL;
        int k_orig = c * 32 + kl;
        float wv = (k_orig < 128) ? W_ih[row * 128 + k_orig]
                                  : W_hh[row * 128 + (k_orig - 128)];
        *(__half*)((char*)d_WT + c * 32768 + SWZ64((uint32_t)(n * 64 + kl * 2))) =
            __float2half_rn(wv);
    }
    if (idx < 512) d_bias[idx] = b_ih[idx] + b_hh[idx];
    if (idx < TT * EE) {
        int t = idx >> 7, e = idx & 127;
        float w0 = W_emb[e * 2], w1 = W_emb[e * 2 + 1], bb = b_emb[e];
        float mu_u = d_mom[t * 5], mu_v = d_mom[t * 5 + 1];
        float vu = d_mom[t * 5 + 2] - mu_u * mu_u;
        float vv = d_mom[t * 5 + 3] - mu_v * mu_v;
        float cuv = d_mom[t * 5 + 4] - mu_u * mu_v;
        float mu = w0 * mu_u + w1 * mu_v + bb;
        float var = w0 * w0 * vu + w1 * w1 * vv + 2.f * w0 * w1 * cuv;
        float sc = g_emb[e] * rsqrtf(var + EPSV);
        d_A[idx] = sc * w0; d_Bc[idx] = sc * w1;
        d_Cc[idx] = sc * (bb - mu) + be_emb[e];
    }
}

__global__ void __launch_bounds__(512, 1)
k_lstm(const float* __restrict__ inp, const float* __restrict__ W_out) {
    extern __shared__ char dsm_raw[];
    const uint32_t rawU = s2u(dsm_raw);
    const uint32_t base = (rawU + 1023) & ~1023u;
    char* dsm = dsm_raw + (base - rawU);
    __half* sAh = (__half*)dsm;
    const uint32_t AhU = base, ringU = base + OFF_R;

    __shared__ float sBias[512];
    __shared__ float sAe[EE], sBe[EE], sCe[EE];
    __shared__ float sUV[BM * 2];
    __shared__ float sH[BM * 130];        // fp32 h for output head
    __shared__ float sWo[DOUT * CC];

    const int tid = threadIdx.x, lane = tid & 31, wid = tid >> 5;
    const int b0 = blockIdx.x * BM;
    const int grp = lane >> 3, li = lane & 7;
    const int rowA = (grp & 1) * 8 + li;
    const int kaddA = (grp >> 1) * 8;

    if (tid < 512) sBias[tid] = d_bias[tid];
    for (int i = tid; i < DOUT * CC; i += 512) sWo[i] = W_out[i];
    for (int i = tid; i < 4096; i += 512) {          // zero h region (cols 128..255)
        int r = i >> 6, q = i & 63;
        *(uint32_t*)(sAh + r * AST + 128 + 2 * q) = 0;
    }
    __syncthreads();

    // prologue (once): chunks 0,1 into ring slots 0,1
    #pragma unroll
    for (int pc = 0; pc < 2; pc++) {
        const char* src = (const char*)d_WT + pc * 32768 + tid * 64;
        uint32_t dst = ringU + pc * 32768 + tid * 64;
        #pragma unroll
        for (int q = 0; q < 4; q++) CPA16(dst + q * 16, src + q * 16);
        COMMIT();
    }

    float cst[16];
    #pragma unroll
    for (int i = 0; i < 16; i++) cst[i] = 0.f;

    for (int t = 0; t < TT; t++) {
        if (tid < BM) {
            float2 uv = *(const float2*)(inp + ((size_t)(b0 + tid) * TT + t) * 2);
            sUV[tid * 2] = uv.x; sUV[tid * 2 + 1] = uv.y;
        }
        if (tid < EE) {
            sAe[tid] = d_A[t * EE + tid];
            sBe[tid] = d_Bc[t * EE + tid];
            sCe[tid] = d_Cc[t * EE + tid];
        }
        __syncthreads();

        // xbn -> A cols 0..127 (single fp16)
        for (int i = tid; i < 4096; i += 512) {
            int r = i >> 6, ep = i & 63, e = 2 * ep;
            float u = sUV[2 * r], v = sUV[2 * r + 1];
            float x0 = fmaxf(fmaf(sAe[e], u, fmaf(sBe[e], v, sCe[e])), 0.f);
            float x1 = fmaxf(fmaf(sAe[e + 1], u, fmaf(sBe[e + 1], v, sCe[e + 1])), 0.f);
            __half2 hp; hp.x = __float2half_rn(x0); hp.y = __float2half_rn(x1);
            *(__half2*)(sAh + r * AST + e) = hp;
        }

        float acc[4][4][4];
        #pragma unroll
        for (int a = 0; a < 4; a++)
            #pragma unroll
            for (int g = 0; g < 4; g++)
                #pragma unroll
                for (int q = 0; q < 4; q++) acc[a][g][q] = 0.f;

        // 8 k-chunks over a 4-slot ring: ONE barrier per chunk.
        // Refill targets slot (c+2)&3 — provably idle (last read 2 syncs ago).
        for (int c = 0; c < 8; c++) {
            WAITG1();
            __syncthreads();
            const uint32_t slotU = ringU + (c & 3) * 32768;
            uint32_t bfr[4][4];
            #pragma unroll
            for (int g = 0; g < 4; g++) {
                uint32_t nrow = (uint32_t)(wid * 32 + g * 8 + li);
                LDSM4(bfr[g], slotU + SWZ64(nrow * 64 + (uint32_t)grp * 16));
            }
            const int kb = c * 32;
            #pragma unroll
            for (int ks = 0; ks < 2; ks++)
                #pragma unroll
                for (int mi = 0; mi < 4; mi++) {
                    uint32_t af[4];
                    LDSM4(af, AhU + (uint32_t)((mi * 16 + rowA) * AST +
                                               kb + ks * 16 + kaddA) * 2);
                    #pragma unroll
                    for (int g = 0; g < 4; g++)
                        MMAF16(acc[mi][g], af, bfr[g][2 * ks], bfr[g][2 * ks + 1]);
                }
            {   // refill slot (c+2)&3 with chunk (c+2)&7 — wraps across steps
                const char* src = (const char*)d_WT + ((c + 2) & 7) * 32768 + tid * 64;
                uint32_t dst = ringU + ((c + 2) & 3) * 32768 + tid * 64;
                #pragma unroll
                for (int q = 0; q < 4; q++) CPA16(dst + q * 16, src + q * 16);
                COMMIT();
            }
        }
        __syncthreads();   // all warps done with chunk-7 MMAs before cell writes h

        // cell update: thread owns channels {ch0, ch0+1}, rows mi*16+(lane>>2)+8*hf
        const int ch0 = wid * 8 + 2 * (lane & 3);
        const float bi0 = sBias[ch0],       bi1 = sBias[ch0 + 1];
        const float bf0 = sBias[128 + ch0], bf1 = sBias[129 + ch0];
        const float bg0 = sBias[256 + ch0], bg1 = sBias[257 + ch0];
        const float bo0 = sBias[384 + ch0], bo1 = sBias[385 + ch0];
        #pragma unroll
        for (int mi = 0; mi < 4; mi++)
            #pragma unroll
            for (int hf = 0; hf < 2; hf++) {
                const int row = mi * 16 + (lane >> 2) + 8 * hf;
                const int q0 = 2 * hf, ci = mi * 4 + 2 * hf;
                float c0 = sigm(acc[mi][1][q0] + bf0) * cst[ci]
                         + sigm(acc[mi][0][q0] + bi0) * tanh_a(acc[mi][2][q0] + bg0);
                float c1 = sigm(acc[mi][1][q0 + 1] + bf1) * cst[ci + 1]
                         + sigm(acc[mi][0][q0 + 1] + bi1) * tanh_a(acc[mi][2][q0 + 1] + bg1);
                cst[ci] = c0; cst[ci + 1] = c1;
                float h0 = sigm(acc[mi][3][q0] + bo0) * tanh_a(c0);
                float h1 = sigm(acc[mi][3][q0 + 1] + bo1) * tanh_a(c1);
                __half2 hp; hp.x = __float2half_rn(h0); hp.y = __float2half_rn(h1);
                *(__half2*)(sAh + row * AST + 128 + ch0) = hp;
                float2 hv; hv.x = h0; hv.y = h1;
                *(float2*)(sH + row * 130 + ch0) = hv;
            }
        __syncthreads();

        // fused output head: y[row][o] = sum_c h[row][c] * Wout[o][c]
        if (tid < 320) {
            const int o = tid >> 6, row = tid & 63;
            const float* hr = sH + row * 130;
            const float* wr = sWo + o * CC;
            float y0 = 0.f, y1 = 0.f, y2 = 0.f, y3 = 0.f;
            #pragma unroll 8
            for (int c2 = 0; c2 < CC; c2 += 4) {
                y0 = fmaf(hr[c2],     wr[c2],     y0);
                y1 = fmaf(hr[c2 + 1], wr[c2 + 1], y1);
                y2 = fmaf(hr[c2 + 2], wr[c2 + 2], y2);
                y3 = fmaf(hr[c2 + 3], wr[c2 + 3], y3);
            }
            d_Y[((size_t)t * BB + b0 + row) * DOUT + o] = (y0 + y1) + (y2 + y3);
        }
        __syncthreads();
    }
}

__global__ void k_final(const float* __restrict__ g_out, const float* __restrict__ be_out,
                        float* __restrict__ out) {
    int t = blockIdx.x, tid = threadIdx.x;
    float s1[DOUT], s2[DOUT];
    #pragma unroll
    for (int o = 0; o < DOUT; o++) { s1[o] = 0.f; s2[o] = 0.f; }
    for (int b = tid; b < BB; b += 256) {
        const float* y = d_Y + ((size_t)t * BB + b) * DOUT;
        #pragma unroll
        for (int o = 0; o < DOUT; o++) { float v = y[o]; s1[o] += v; s2[o] += v * v; }
    }
    __shared__ float r1[DOUT][256], r2[DOUT][256];
    #pragma unroll
    for (int o = 0; o < DOUT; o++) { r1[o][tid] = s1[o]; r2[o][tid] = s2[o]; }
    __syncthreads();
    for (int s = 128; s > 0; s >>= 1) {
        if (tid < s)
            #pragma unroll
            for (int o = 0; o < DOUT; o++) {
                r1[o][tid] += r1[o][tid + s]; r2[o][tid] += r2[o][tid + s];
            }
        __syncthreads();
    }
    __shared__ float mu[DOUT], rs[DOUT], bb[DOUT];
    if (tid < DOUT) {
        float m = r1[tid][0] * (1.0f / BB);
        float v = r2[tid][0] * (1.0f / BB) - m * m;
        mu[tid] = m; rs[tid] = rsqrtf(v + EPSV) * g_out[tid]; bb[tid] = be_out[tid];
    }
    __syncthreads();
    for (int b = tid; b < BB; b += 256) {
        const float* y = d_Y + ((size_t)t * BB + b) * DOUT;
        float* op = out + ((size_t)b * TT + t) * DOUT;
        #pragma unroll
        for (int o = 0; o < DOUT; o++)
            op[o] = fmaxf(fmaf(y[o] - mu[o], rs[o], bb[o]), 0.f);
    }
}

extern "C" void kernel_launch(void* const* d_in, const int* in_sizes, int n_in,
                              void* d_out, int out_size) {
    const float* inp    = (const float*)d_in[0];
    const float* W_emb  = (const float*)d_in[1];
    const float* b_emb  = (const float*)d_in[2];
    const float* g_emb  = (const float*)d_in[3];
    const float* be_emb = (const float*)d_in[4];
    const float* W_ih   = (const float*)d_in[5];
    const float* W_hh   = (const float*)d_in[6];
    const float* b_ih   = (const float*)d_in[7];
    const float* b_hh   = (const float*)d_in[8];
    const float* W_out  = (const float*)d_in[9];
    const float* g_out  = (const float*)d_in[11];
    const float* be_out = (const float*)d_in[12];
    float* out = (float*)d_out;
    // b_out (d_in[10]) provably cancels in batch-BN; unused.

    cudaFuncSetAttribute(k_lstm, cudaFuncAttributeMaxDynamicSharedMemorySize, DSM_REQ);

    k_moments<<<TT, 256>>>(inp);
    k_prep<<<512, 256>>>(W_emb, b_emb, g_emb, be_emb, W_ih, W_hh, b_ih, b_hh);
    k_lstm<<<NCTA, 512, DSM_REQ>>>(inp, W_out);
    k_final<<<TT, 256>>>(g_out, be_out, out);
}